// round 5
// baseline (speedup 1.0000x reference)
#include <cuda_runtime.h>
#include <cuda_bf16.h>
#include <cstdint>

#define HH 128
#define WW 128
#define HWSZ (HH*WW)
#define CIN 64
#define COUT 128
#define NB 4
#define KTOT 576      // CIN * 9
#define NCHUNK 18     // K chunks of 32

// ---------------- device scratch ----------------
__device__ float g_offmod[NB * 27 * HWSZ];              // offsets(18) + modulators(9)
__device__ float g_xt[NB * HWSZ * CIN];                 // x transposed: [b][hw][c]
__device__ __nv_bfloat16 g_wh[NCHUNK * 128 * 32];       // W hi  [chunk][oc][kl]
__device__ __nv_bfloat16 g_wl[NCHUNK * 128 * 32];       // W lo

__device__ __forceinline__ uint32_t smem_u32(const void* p) {
    uint32_t a;
    asm("{ .reg .u64 t; cvta.to.shared.u64 t, %1; cvt.u32.u64 %0, t; }" : "=r"(a) : "l"(p));
    return a;
}

__device__ __forceinline__ void ldm4(uint32_t* r, uint32_t addr) {
    asm volatile("ldmatrix.sync.aligned.m8n8.x4.shared.b16 {%0,%1,%2,%3}, [%4];"
                 : "=r"(r[0]), "=r"(r[1]), "=r"(r[2]), "=r"(r[3]) : "r"(addr));
}
__device__ __forceinline__ void mma_bf16(float* c, const uint32_t* a, const uint32_t* b) {
    asm volatile("mma.sync.aligned.m16n8k16.row.col.f32.bf16.bf16.f32 "
                 "{%0,%1,%2,%3}, {%4,%5,%6,%7}, {%8,%9}, {%0,%1,%2,%3};"
                 : "+f"(c[0]), "+f"(c[1]), "+f"(c[2]), "+f"(c[3])
                 : "r"(a[0]), "r"(a[1]), "r"(a[2]), "r"(a[3]), "r"(b[0]), "r"(b[1]));
}
#define BARSYNC(id) asm volatile("bar.sync %0, 320;" :: "r"(id) : "memory")
#define BARARR(id)  asm volatile("bar.arrive %0, 320;" :: "r"(id) : "memory")
#define MEMBAR_CTA() asm volatile("membar.cta;" ::: "memory")

// ---------------------------------------------------------------------------
// x transpose: [b][c][hw] -> [b][hw][c]
// ---------------------------------------------------------------------------
__global__ void xt_kernel(const float* __restrict__ x) {
    __shared__ float sm[64][65];
    const int tid = threadIdx.x;
    const int b   = blockIdx.y;
    const int hw0 = blockIdx.x * 64;
    const float* xb = x + (size_t)b * CIN * HWSZ;
    #pragma unroll
    for (int it = 0; it < 16; it++) {
        int c   = (tid >> 6) + it * 4;
        int hwl = tid & 63;
        sm[hwl][c] = xb[c * HWSZ + hw0 + hwl];
    }
    __syncthreads();
    float* xtb = g_xt + ((size_t)b * HWSZ + hw0) * CIN;
    #pragma unroll
    for (int it = 0; it < 16; it++) {
        int hwl = (tid >> 6) + it * 4;
        int cl  = tid & 63;
        xtb[hwl * CIN + cl] = sm[hwl][cl];
    }
}

// ---------------------------------------------------------------------------
// W prep: split into bf16 hi/lo, K reordered as k_new = tap*64 + c
// ---------------------------------------------------------------------------
__global__ void wprep_kernel(const float* __restrict__ w_reg) {
    int i = blockIdx.x * 256 + threadIdx.x;
    if (i >= COUT * KTOT) return;
    int oc = i / KTOT;
    int kn = i - oc * KTOT;
    int tap = kn >> 6;
    int c   = kn & 63;
    float v = w_reg[oc * KTOT + c * 9 + tap];
    __nv_bfloat16 h = __float2bfloat16_rn(v);
    float lo = v - __bfloat162float(h);
    int chunk = kn >> 5;
    int kl    = kn & 31;
    g_wh[(chunk * 128 + oc) * 32 + kl] = h;
    g_wl[(chunk * 128 + oc) * 32 + kl] = __float2bfloat16_rn(lo);
}

// ---------------------------------------------------------------------------
// Kernel A: fused offset + modulator 3x3 conv (SIMT fp32)
// ---------------------------------------------------------------------------
#define ATH 16
#define ATW 32
#define AHH 18
#define AHW 34
#define XT (CIN*AHH*AHW)

__global__ void __launch_bounds__(256, 1) offmod_kernel(
    const float* __restrict__ x,
    const float* __restrict__ w_off, const float* __restrict__ b_off,
    const float* __restrict__ w_mod, const float* __restrict__ b_mod)
{
    extern __shared__ float sm[];
    float* xs = sm;
    float* ws = sm + XT;

    const int tid = threadIdx.x;
    const int b   = blockIdx.z;
    const int ty0 = blockIdx.y * ATH;
    const int tx0 = blockIdx.x * ATW;
    const float* xb = x + (size_t)b * CIN * HWSZ;

    for (int i = tid; i < XT; i += 256) {
        int c  = i / (AHH*AHW);
        int r  = i - c * (AHH*AHW);
        int yy = r / AHW;
        int xx = r - yy * AHW;
        int gy = ty0 + yy - 1;
        int gx = tx0 + xx - 1;
        float v = 0.f;
        if (gy >= 0 && gy < HH && gx >= 0 && gx < WW)
            v = xb[c * HWSZ + gy * WW + gx];
        xs[i] = v;
    }
    for (int i = tid; i < CIN*9*27; i += 256) {
        int o  = i % 27;
        int ck = i / 27;
        int c  = ck / 9;
        int k  = ck - c * 9;
        float v = (o < 18) ? w_off[(o * CIN + c) * 9 + k]
                           : w_mod[((o - 18) * CIN + c) * 9 + k];
        ws[ck * 28 + o] = v;
    }
    __syncthreads();

    const int px = tid & 31;
    const int py = tid >> 5;

    float acc0[27], acc1[27];
    #pragma unroll
    for (int o = 0; o < 27; o++) { acc0[o] = 0.f; acc1[o] = 0.f; }

    for (int c = 0; c < CIN; c++) {
        const float* xc = xs + c * (AHH*AHW);
        #pragma unroll
        for (int ky = 0; ky < 3; ky++) {
            #pragma unroll
            for (int kx = 0; kx < 3; kx++) {
                float xv0 = xc[(py + ky) * AHW + px + kx];
                float xv1 = xc[(py + 8 + ky) * AHW + px + kx];
                const float4* wp = (const float4*)(ws + (c * 9 + ky * 3 + kx) * 28);
                #pragma unroll
                for (int q = 0; q < 7; q++) {
                    float4 t = wp[q];
                    const int o = 4 * q;
                    acc0[o+0] += t.x * xv0;  acc1[o+0] += t.x * xv1;
                    if (o + 1 < 27) { acc0[o+1] += t.y * xv0;  acc1[o+1] += t.y * xv1; }
                    if (o + 2 < 27) { acc0[o+2] += t.z * xv0;  acc1[o+2] += t.z * xv1; }
                    if (o + 3 < 27) { acc0[o+3] += t.w * xv0;  acc1[o+3] += t.w * xv1; }
                }
            }
        }
    }

    const int gy = ty0 + py;
    const int gx = tx0 + px;
    float* outp = g_offmod + (size_t)b * 27 * HWSZ;
    #pragma unroll
    for (int o = 0; o < 27; o++) {
        float bias = (o < 18) ? b_off[o] : b_mod[o - 18];
        float v0 = acc0[o] + bias;
        float v1 = acc1[o] + bias;
        if (o >= 18) {
            v0 = 2.f / (1.f + __expf(-v0));
            v1 = 2.f / (1.f + __expf(-v1));
        }
        outp[o * HWSZ + gy * WW + gx]       = v0;
        outp[o * HWSZ + (gy + 8) * WW + gx] = v1;
    }
}

// ---------------------------------------------------------------------------
// Kernel B: warp-specialized bf16 mma.sync GEMM with bilinear sampling.
// Block = one (row y, batch b): D[128 oc][128 px], K = 576 in 18 chunks of 32.
// Warps 0-7 consume (mma), warps 8-9 produce (sample + W copy).
// Producer lane map: 4 px x 8 ch-lanes -> each LDG.128 hits exactly 4 fully
// consumed 128B lines (chunk = 32 channels = 128 bytes contiguous in g_xt).
// ---------------------------------------------------------------------------
#define TBC 320
#define ROWB 80                 // smem row stride bytes (conflict-free for ldmatrix)
#define MATB (128 * ROWB)       // 10240
#define STAGEB (4 * MATB)       // 40960
#define CWB (2 * STAGEB)        // 81920: cw table offset
#define CIB (CWB + 4 * 1152 * 4)
#define SMEMB_TOTAL (CIB + 4 * 1152 * 4)   // 118784

#define BFULL0 1
#define BFULL1 2
#define BEMPTY0 3
#define BEMPTY1 4

__global__ void __launch_bounds__(TBC, 1) dcn_kernel(float* __restrict__ out)
{
    extern __shared__ char smb[];
    const uint32_t sb = smem_u32(smb);
    float* scw = (float*)(smb + CWB);   // [4][1152] corner weights
    int*   sci = (int*)(smb + CIB);     // [4][1152] corner linear indices

    const int tid = threadIdx.x;
    const int wid = tid >> 5;
    const int lid = tid & 31;
    const int y   = blockIdx.x;
    const int b   = blockIdx.y;
    const float* offm = g_offmod + (size_t)b * 27 * HWSZ;

    // Phase 0 (all threads): bilinear coords for 9 taps x 128 px
    for (int i = tid; i < 1152; i += TBC) {
        int k = i >> 7;
        int p = i & 127;
        int lin = y * WW + p;
        float dy = offm[(2*k)   * HWSZ + lin];
        float dx = offm[(2*k+1) * HWSZ + lin];
        float m  = offm[(18+k)  * HWSZ + lin];
        float pyf = (float)(y + k / 3 - 1) + dy;
        float pxf = (float)(p + k % 3 - 1) + dx;
        float fy = floorf(pyf);
        float fx = floorf(pxf);
        float ty = pyf - fy;
        float tx = pxf - fx;
        int iy0 = (int)fy, ix0 = (int)fx;
        int iy1 = iy0 + 1, ix1 = ix0 + 1;
        float vy0 = (iy0 >= 0 && iy0 <= HH-1) ? 1.f : 0.f;
        float vy1 = (iy1 >= 0 && iy1 <= HH-1) ? 1.f : 0.f;
        float vx0 = (ix0 >= 0 && ix0 <= WW-1) ? 1.f : 0.f;
        float vx1 = (ix1 >= 0 && ix1 <= WW-1) ? 1.f : 0.f;
        int cy0 = min(max(iy0, 0), HH-1);
        int cy1 = min(max(iy1, 0), HH-1);
        int cx0 = min(max(ix0, 0), WW-1);
        int cx1 = min(max(ix1, 0), WW-1);
        scw[i       ] = (1.f - ty) * (1.f - tx) * m * vy0 * vx0;
        scw[1152 + i] = (1.f - ty) * tx         * m * vy0 * vx1;
        scw[2304 + i] = ty * (1.f - tx)         * m * vy1 * vx0;
        scw[3456 + i] = ty * tx                 * m * vy1 * vx1;
        sci[i       ] = cy0 * WW + cx0;
        sci[1152 + i] = cy0 * WW + cx1;
        sci[2304 + i] = cy1 * WW + cx0;
        sci[3456 + i] = cy1 * WW + cx1;
    }
    __syncthreads();

    if (wid < 8) {
        // ---------------- consumers ----------------
        const int warp_m = wid & 3;       // oc tile of 32
        const int warp_n = wid >> 2;      // px tile of 64
        const int l = lid;
        const uint32_t aoffl = (uint32_t)((l & 15) * ROWB + (l >> 4) * 16);
        const uint32_t boffl = (uint32_t)(((l & 7) + ((l >> 4) ? 8 : 0)) * ROWB + ((l >> 3) & 1) * 16);

        float c[2][8][4];
        #pragma unroll
        for (int i = 0; i < 2; i++)
            #pragma unroll
            for (int j = 0; j < 8; j++)
                #pragma unroll
                for (int q = 0; q < 4; q++) c[i][j][q] = 0.f;

        for (int t = 0; t < NCHUNK; t++) {
            const int s = t & 1;
            BARSYNC(BFULL0 + s);
            const uint32_t stg = sb + (uint32_t)(s * STAGEB);
            #pragma unroll
            for (int ks = 0; ks < 2; ks++) {
                const uint32_t abase = stg + (uint32_t)(warp_m * 32 * ROWB + ks * 32) + aoffl;
                uint32_t ah[2][4], al[2][4];
                ldm4(ah[0], abase);
                ldm4(ah[1], abase + 16 * ROWB);
                ldm4(al[0], abase + MATB);
                ldm4(al[1], abase + MATB + 16 * ROWB);
                const uint32_t bbase = stg + (uint32_t)(2 * MATB + warp_n * 64 * ROWB + ks * 32) + boffl;
                uint32_t bh[8][2], bl[8][2];
                #pragma unroll
                for (int jj = 0; jj < 4; jj++) {
                    uint32_t tmp[4];
                    ldm4(tmp, bbase + (uint32_t)(jj * 16 * ROWB));
                    bh[2*jj][0] = tmp[0]; bh[2*jj][1] = tmp[1];
                    bh[2*jj+1][0] = tmp[2]; bh[2*jj+1][1] = tmp[3];
                    ldm4(tmp, bbase + (uint32_t)(MATB + jj * 16 * ROWB));
                    bl[2*jj][0] = tmp[0]; bl[2*jj][1] = tmp[1];
                    bl[2*jj+1][0] = tmp[2]; bl[2*jj+1][1] = tmp[3];
                }
                #pragma unroll
                for (int i = 0; i < 2; i++) {
                    #pragma unroll
                    for (int j = 0; j < 8; j++) {
                        mma_bf16(c[i][j], ah[i], bh[j]);
                        mma_bf16(c[i][j], ah[i], bl[j]);
                        mma_bf16(c[i][j], al[i], bh[j]);
                    }
                }
            }
            BARARR(BEMPTY0 + s);
        }

        // epilogue
        const int mrow = l >> 2;
        const int ncol = (l & 3) * 2;
        #pragma unroll
        for (int i = 0; i < 2; i++) {
            #pragma unroll
            for (int j = 0; j < 8; j++) {
                int m0 = warp_m * 32 + i * 16 + mrow;
                int n  = warp_n * 64 + j * 8 + ncol;
                float* p0 = out + ((size_t)(b * COUT + m0)) * HWSZ + y * WW + n;
                *(float2*)p0 = make_float2(c[i][j][0], c[i][j][1]);
                *(float2*)(p0 + 8 * HWSZ) = make_float2(c[i][j][2], c[i][j][3]);
            }
        }
    } else {
        // ---------------- producers ----------------
        const int tl   = tid - 256;   // 0..63
        const int wp   = tl >> 5;     // producer warp 0/1
        const int pxo  = (lid >> 3);  // 0..3 pixel within group
        const int chl  = lid & 7;     // 0..7 channel-lane (4 floats each)
        const float* __restrict__ xtb = g_xt + (size_t)b * HWSZ * CIN;

        for (int t = 0; t < NCHUNK; t++) {
            const int s = t & 1;
            if (t >= 2) BARSYNC(BEMPTY0 + s);
            char* stg = smb + s * STAGEB;

            // W hi/lo copy: 2 mats x 128 rows x 4 float4
            {
                const char* srcH = (const char*)g_wh + (size_t)t * 128 * 64;
                const char* srcL = (const char*)g_wl + (size_t)t * 128 * 64;
                #pragma unroll
                for (int it = 0; it < 16; it++) {
                    int i = tl + it * 64;      // 0..1023
                    int mat = i >> 9;
                    int rr  = (i >> 2) & 127;
                    int c4  = i & 3;
                    const char* src = (mat ? srcL : srcH) + rr * 64 + c4 * 16;
                    float4 v = *(const float4*)src;
                    *(float4*)(stg + mat * MATB + rr * ROWB + c4 * 16) = v;
                }
            }

            // Sampling: tap = t/2, channels cbase..cbase+31 (= 128B per px-corner)
            const int tap   = t >> 1;
            const int cbase = (t & 1) << 5;
            char* sh = stg + 2 * MATB;
            char* sl = stg + 3 * MATB;
            const float* __restrict__ xq = xtb + cbase;

            #pragma unroll 2
            for (int it = 0; it < 16; it++) {
                const int px  = wp * 64 + it * 4 + pxo;
                const int idx = tap * 128 + px;
                const int i0 = sci[idx], i1 = sci[1152 + idx], i2 = sci[2304 + idx], i3 = sci[3456 + idx];
                const float4 a0 = *(const float4*)(xq + (size_t)i0 * CIN + chl * 4);
                const float4 a1 = *(const float4*)(xq + (size_t)i1 * CIN + chl * 4);
                const float4 a2 = *(const float4*)(xq + (size_t)i2 * CIN + chl * 4);
                const float4 a3 = *(const float4*)(xq + (size_t)i3 * CIN + chl * 4);
                const float w0 = scw[idx], w1 = scw[1152 + idx], w2 = scw[2304 + idx], w3 = scw[3456 + idx];
                float v0 = w0*a0.x + w1*a1.x + w2*a2.x + w3*a3.x;
                float v1 = w0*a0.y + w1*a1.y + w2*a2.y + w3*a3.y;
                float v2 = w0*a0.z + w1*a1.z + w2*a2.z + w3*a3.z;
                float v3 = w0*a0.w + w1*a1.w + w2*a2.w + w3*a3.w;
                __nv_bfloat16 h0 = __float2bfloat16_rn(v0);
                __nv_bfloat16 h1 = __float2bfloat16_rn(v1);
                __nv_bfloat16 h2 = __float2bfloat16_rn(v2);
                __nv_bfloat16 h3 = __float2bfloat16_rn(v3);
                __nv_bfloat16 l0 = __float2bfloat16_rn(v0 - __bfloat162float(h0));
                __nv_bfloat16 l1 = __float2bfloat16_rn(v1 - __bfloat162float(h1));
                __nv_bfloat16 l2 = __float2bfloat16_rn(v2 - __bfloat162float(h2));
                __nv_bfloat16 l3 = __float2bfloat16_rn(v3 - __bfloat162float(h3));
                uint32_t hp0 = (uint32_t)__bfloat16_as_ushort(h0) | ((uint32_t)__bfloat16_as_ushort(h1) << 16);
                uint32_t hp1 = (uint32_t)__bfloat16_as_ushort(h2) | ((uint32_t)__bfloat16_as_ushort(h3) << 16);
                uint32_t lp0 = (uint32_t)__bfloat16_as_ushort(l0) | ((uint32_t)__bfloat16_as_ushort(l1) << 16);
                uint32_t lp1 = (uint32_t)__bfloat16_as_ushort(l2) | ((uint32_t)__bfloat16_as_ushort(l3) << 16);
                *(uint2*)(sh + px * ROWB + chl * 8) = make_uint2(hp0, hp1);
                *(uint2*)(sl + px * ROWB + chl * 8) = make_uint2(lp0, lp1);
            }

            MEMBAR_CTA();
            BARARR(BFULL0 + s);
        }
    }
}

// ---------------------------------------------------------------------------
extern "C" void kernel_launch(void* const* d_in, const int* in_sizes, int n_in,
                              void* d_out, int out_size)
{
    const float* x     = (const float*)d_in[0];
    const float* w_off = (const float*)d_in[1];
    const float* b_off = (const float*)d_in[2];
    const float* w_mod = (const float*)d_in[3];
    const float* b_mod = (const float*)d_in[4];
    const float* w_reg = (const float*)d_in[5];
    float* out = (float*)d_out;
    (void)in_sizes; (void)n_in; (void)out_size;

    const int smA = (XT + CIN * 9 * 28) * 4;
    cudaFuncSetAttribute(offmod_kernel, cudaFuncAttributeMaxDynamicSharedMemorySize, smA);
    cudaFuncSetAttribute(dcn_kernel,    cudaFuncAttributeMaxDynamicSharedMemorySize, SMEMB_TOTAL);

    wprep_kernel<<<(COUT * KTOT + 255) / 256, 256>>>(w_reg);

    dim3 gT(HWSZ / 64, NB);
    xt_kernel<<<gT, 256>>>(x);

    dim3 gA(WW / ATW, HH / ATH, NB);
    offmod_kernel<<<gA, 256, smA>>>(x, w_off, b_off, w_mod, b_mod);

    dim3 gB(HH, NB);
    dcn_kernel<<<gB, TBC, SMEMB_TOTAL>>>(out);
}

// round 7
// speedup vs baseline: 1.8888x; 1.8888x over previous
#include <cuda_runtime.h>
#include <cuda_bf16.h>
#include <cstdint>

#define HH 128
#define WW 128
#define HWSZ (HH*WW)
#define CIN 64
#define COUT 128
#define NB 4
#define KTOT 576      // CIN * 9
#define NCHUNK 18     // K chunks of 32

// ---------------- device scratch ----------------
__device__ float g_offmod[NB * 27 * HWSZ];              // offsets(18) + modulators(9)
__device__ float g_xt[NB * HWSZ * CIN];                 // x transposed: [b][hw][c]
__device__ __nv_bfloat16 g_wh[NCHUNK * 128 * 32];       // W hi  [chunk][oc][kl]
__device__ __nv_bfloat16 g_wl[NCHUNK * 128 * 32];       // W lo

__device__ __forceinline__ uint32_t smem_u32(const void* p) {
    uint32_t a;
    asm("{ .reg .u64 t; cvta.to.shared.u64 t, %1; cvt.u32.u64 %0, t; }" : "=r"(a) : "l"(p));
    return a;
}
__device__ __forceinline__ void ldm4(uint32_t* r, uint32_t addr) {
    asm volatile("ldmatrix.sync.aligned.m8n8.x4.shared.b16 {%0,%1,%2,%3}, [%4];"
                 : "=r"(r[0]), "=r"(r[1]), "=r"(r[2]), "=r"(r[3]) : "r"(addr));
}
__device__ __forceinline__ void mma_bf16(float* c, const uint32_t* a, const uint32_t* b) {
    asm volatile("mma.sync.aligned.m16n8k16.row.col.f32.bf16.bf16.f32 "
                 "{%0,%1,%2,%3}, {%4,%5,%6,%7}, {%8,%9}, {%0,%1,%2,%3};"
                 : "+f"(c[0]), "+f"(c[1]), "+f"(c[2]), "+f"(c[3])
                 : "r"(a[0]), "r"(a[1]), "r"(a[2]), "r"(a[3]), "r"(b[0]), "r"(b[1]));
}
__device__ __forceinline__ void cp16(uint32_t dst, const void* src) {
    asm volatile("cp.async.cg.shared.global [%0], [%1], 16;" :: "r"(dst), "l"(src));
}
#define CPCOMMIT() asm volatile("cp.async.commit_group;" ::: "memory")
#define CPWAIT0()  asm volatile("cp.async.wait_group 0;" ::: "memory")

// ---------------------------------------------------------------------------
// x transpose: [b][c][hw] -> [b][hw][c]
// ---------------------------------------------------------------------------
__global__ void xt_kernel(const float* __restrict__ x) {
    __shared__ float sm[64][65];
    const int tid = threadIdx.x;
    const int b   = blockIdx.y;
    const int hw0 = blockIdx.x * 64;
    const float* xb = x + (size_t)b * CIN * HWSZ;
    #pragma unroll
    for (int it = 0; it < 16; it++) {
        int c   = (tid >> 6) + it * 4;
        int hwl = tid & 63;
        sm[hwl][c] = xb[c * HWSZ + hw0 + hwl];
    }
    __syncthreads();
    float* xtb = g_xt + ((size_t)b * HWSZ + hw0) * CIN;
    #pragma unroll
    for (int it = 0; it < 16; it++) {
        int hwl = (tid >> 6) + it * 4;
        int cl  = tid & 63;
        xtb[hwl * CIN + cl] = sm[hwl][cl];
    }
}

// ---------------------------------------------------------------------------
// W prep: split into bf16 hi/lo, K reordered as k_new = tap*64 + c
// ---------------------------------------------------------------------------
__global__ void wprep_kernel(const float* __restrict__ w_reg) {
    int i = blockIdx.x * 256 + threadIdx.x;
    if (i >= COUT * KTOT) return;
    int oc = i / KTOT;
    int kn = i - oc * KTOT;
    int tap = kn >> 6;
    int c   = kn & 63;
    float v = w_reg[oc * KTOT + c * 9 + tap];
    __nv_bfloat16 h = __float2bfloat16_rn(v);
    float lo = v - __bfloat162float(h);
    int chunk = kn >> 5;
    int kl    = kn & 31;
    g_wh[(chunk * 128 + oc) * 32 + kl] = h;
    g_wl[(chunk * 128 + oc) * 32 + kl] = __float2bfloat16_rn(lo);
}

// ---------------------------------------------------------------------------
// Kernel A: fused offset + modulator 3x3 conv (SIMT fp32)
// ---------------------------------------------------------------------------
#define ATH 16
#define ATW 32
#define AHH 18
#define AHW 34
#define XT (CIN*AHH*AHW)

__global__ void __launch_bounds__(256, 1) offmod_kernel(
    const float* __restrict__ x,
    const float* __restrict__ w_off, const float* __restrict__ b_off,
    const float* __restrict__ w_mod, const float* __restrict__ b_mod)
{
    extern __shared__ float sm[];
    float* xs = sm;
    float* ws = sm + XT;

    const int tid = threadIdx.x;
    const int b   = blockIdx.z;
    const int ty0 = blockIdx.y * ATH;
    const int tx0 = blockIdx.x * ATW;
    const float* xb = x + (size_t)b * CIN * HWSZ;

    for (int i = tid; i < XT; i += 256) {
        int c  = i / (AHH*AHW);
        int r  = i - c * (AHH*AHW);
        int yy = r / AHW;
        int xx = r - yy * AHW;
        int gy = ty0 + yy - 1;
        int gx = tx0 + xx - 1;
        float v = 0.f;
        if (gy >= 0 && gy < HH && gx >= 0 && gx < WW)
            v = xb[c * HWSZ + gy * WW + gx];
        xs[i] = v;
    }
    for (int i = tid; i < CIN*9*27; i += 256) {
        int o  = i % 27;
        int ck = i / 27;
        int c  = ck / 9;
        int k  = ck - c * 9;
        float v = (o < 18) ? w_off[(o * CIN + c) * 9 + k]
                           : w_mod[((o - 18) * CIN + c) * 9 + k];
        ws[ck * 28 + o] = v;
    }
    __syncthreads();

    const int px = tid & 31;
    const int py = tid >> 5;

    float acc0[27], acc1[27];
    #pragma unroll
    for (int o = 0; o < 27; o++) { acc0[o] = 0.f; acc1[o] = 0.f; }

    for (int c = 0; c < CIN; c++) {
        const float* xc = xs + c * (AHH*AHW);
        #pragma unroll
        for (int ky = 0; ky < 3; ky++) {
            #pragma unroll
            for (int kx = 0; kx < 3; kx++) {
                float xv0 = xc[(py + ky) * AHW + px + kx];
                float xv1 = xc[(py + 8 + ky) * AHW + px + kx];
                const float4* wp = (const float4*)(ws + (c * 9 + ky * 3 + kx) * 28);
                #pragma unroll
                for (int q = 0; q < 7; q++) {
                    float4 t = wp[q];
                    const int o = 4 * q;
                    acc0[o+0] += t.x * xv0;  acc1[o+0] += t.x * xv1;
                    if (o + 1 < 27) { acc0[o+1] += t.y * xv0;  acc1[o+1] += t.y * xv1; }
                    if (o + 2 < 27) { acc0[o+2] += t.z * xv0;  acc1[o+2] += t.z * xv1; }
                    if (o + 3 < 27) { acc0[o+3] += t.w * xv0;  acc1[o+3] += t.w * xv1; }
                }
            }
        }
    }

    const int gy = ty0 + py;
    const int gx = tx0 + px;
    float* outp = g_offmod + (size_t)b * 27 * HWSZ;
    #pragma unroll
    for (int o = 0; o < 27; o++) {
        float bias = (o < 18) ? b_off[o] : b_mod[o - 18];
        float v0 = acc0[o] + bias;
        float v1 = acc1[o] + bias;
        if (o >= 18) {
            v0 = 2.f / (1.f + __expf(-v0));
            v1 = 2.f / (1.f + __expf(-v1));
        }
        outp[o * HWSZ + gy * WW + gx]       = v0;
        outp[o * HWSZ + (gy + 8) * WW + gx] = v1;
    }
}

// ---------------------------------------------------------------------------
// Kernel B: homogeneous software-pipelined bf16 mma GEMM + sampling.
// 256 threads (8 warps). Every warp: prefetch gathers for chunk t+1 (regs),
// cp.async W for t+1, run mma on chunk t, combine+STS t+1, one sync/chunk.
// ---------------------------------------------------------------------------
#define TBC 256
#define ROWB 80                 // smem row stride bytes (conflict-free for ldmatrix)
#define MATB (128 * ROWB)       // 10240
#define STAGEB (4 * MATB)       // 40960: Whi | Wlo | Shi | Slo
#define CWB (2 * STAGEB)        // 81920
#define CIB (CWB + 4 * 1152 * 4)
#define SMEMB_TOTAL (CIB + 4 * 1152 * 4)   // 118784

struct Slot {
    float4 a[4];
    float  w[4];
};

__device__ __forceinline__ void gather_slot(Slot& s, int tap, int px, const float* __restrict__ xq,
                                            int chl, const float* scw, const int* sci) {
    int idx = tap * 128 + px;
    s.w[0] = scw[idx]; s.w[1] = scw[idx+1152]; s.w[2] = scw[idx+2304]; s.w[3] = scw[idx+3456];
    int i0 = sci[idx], i1 = sci[idx+1152], i2 = sci[idx+2304], i3 = sci[idx+3456];
    s.a[0] = *(const float4*)(xq + (size_t)i0 * CIN + chl * 4);
    s.a[1] = *(const float4*)(xq + (size_t)i1 * CIN + chl * 4);
    s.a[2] = *(const float4*)(xq + (size_t)i2 * CIN + chl * 4);
    s.a[3] = *(const float4*)(xq + (size_t)i3 * CIN + chl * 4);
}

__device__ __forceinline__ void combine_slot(const Slot& s, char* sh, char* sl, int px, int chl) {
    float v0 = s.w[0]*s.a[0].x + s.w[1]*s.a[1].x + s.w[2]*s.a[2].x + s.w[3]*s.a[3].x;
    float v1 = s.w[0]*s.a[0].y + s.w[1]*s.a[1].y + s.w[2]*s.a[2].y + s.w[3]*s.a[3].y;
    float v2 = s.w[0]*s.a[0].z + s.w[1]*s.a[1].z + s.w[2]*s.a[2].z + s.w[3]*s.a[3].z;
    float v3 = s.w[0]*s.a[0].w + s.w[1]*s.a[1].w + s.w[2]*s.a[2].w + s.w[3]*s.a[3].w;
    __nv_bfloat16 h0 = __float2bfloat16_rn(v0);
    __nv_bfloat16 h1 = __float2bfloat16_rn(v1);
    __nv_bfloat16 h2 = __float2bfloat16_rn(v2);
    __nv_bfloat16 h3 = __float2bfloat16_rn(v3);
    __nv_bfloat16 l0 = __float2bfloat16_rn(v0 - __bfloat162float(h0));
    __nv_bfloat16 l1 = __float2bfloat16_rn(v1 - __bfloat162float(h1));
    __nv_bfloat16 l2 = __float2bfloat16_rn(v2 - __bfloat162float(h2));
    __nv_bfloat16 l3 = __float2bfloat16_rn(v3 - __bfloat162float(h3));
    uint32_t hp0 = (uint32_t)__bfloat16_as_ushort(h0) | ((uint32_t)__bfloat16_as_ushort(h1) << 16);
    uint32_t hp1 = (uint32_t)__bfloat16_as_ushort(h2) | ((uint32_t)__bfloat16_as_ushort(h3) << 16);
    uint32_t lp0 = (uint32_t)__bfloat16_as_ushort(l0) | ((uint32_t)__bfloat16_as_ushort(l1) << 16);
    uint32_t lp1 = (uint32_t)__bfloat16_as_ushort(l2) | ((uint32_t)__bfloat16_as_ushort(l3) << 16);
    *(uint2*)(sh + px * ROWB + chl * 8) = make_uint2(hp0, hp1);
    *(uint2*)(sl + px * ROWB + chl * 8) = make_uint2(lp0, lp1);
}

__device__ __forceinline__ void wcopy_async(int chunk, uint32_t stg, int tid) {
    const char* srcH = (const char*)g_wh + (size_t)chunk * 128 * 64;
    const char* srcL = (const char*)g_wl + (size_t)chunk * 128 * 64;
    #pragma unroll
    for (int it = 0; it < 4; it++) {
        int i = tid + it * 256;     // 0..1023
        int mat = i >> 9;
        int rr  = (i >> 2) & 127;
        int c4  = i & 3;
        const char* src = (mat ? srcL : srcH) + rr * 64 + c4 * 16;
        cp16(stg + (uint32_t)(mat * MATB + rr * ROWB + c4 * 16), src);
    }
}

__device__ __forceinline__ void do_kstep(uint32_t stg, int ks, int warp_m, int warp_n,
                                         uint32_t aoffl, uint32_t boffl, float c[2][8][4]) {
    const uint32_t abase = stg + (uint32_t)(warp_m * 32 * ROWB + ks * 32) + aoffl;
    uint32_t ah[2][4], al[2][4];
    ldm4(ah[0], abase);
    ldm4(ah[1], abase + 16 * ROWB);
    ldm4(al[0], abase + MATB);
    ldm4(al[1], abase + MATB + 16 * ROWB);
    const uint32_t bbase = stg + (uint32_t)(2 * MATB + warp_n * 64 * ROWB + ks * 32) + boffl;
    uint32_t bh[8][2], bl[8][2];
    #pragma unroll
    for (int jj = 0; jj < 4; jj++) {
        uint32_t tmp[4];
        ldm4(tmp, bbase + (uint32_t)(jj * 16 * ROWB));
        bh[2*jj][0] = tmp[0]; bh[2*jj][1] = tmp[1];
        bh[2*jj+1][0] = tmp[2]; bh[2*jj+1][1] = tmp[3];
        ldm4(tmp, bbase + (uint32_t)(MATB + jj * 16 * ROWB));
        bl[2*jj][0] = tmp[0]; bl[2*jj][1] = tmp[1];
        bl[2*jj+1][0] = tmp[2]; bl[2*jj+1][1] = tmp[3];
    }
    #pragma unroll
    for (int i = 0; i < 2; i++) {
        #pragma unroll
        for (int j = 0; j < 8; j++) {
            mma_bf16(c[i][j], ah[i], bh[j]);
            mma_bf16(c[i][j], ah[i], bl[j]);
            mma_bf16(c[i][j], al[i], bh[j]);
        }
    }
}

__global__ void __launch_bounds__(TBC) dcn_kernel(float* __restrict__ out)
{
    extern __shared__ char smb[];
    const uint32_t sb = smem_u32(smb);
    float* scw = (float*)(smb + CWB);
    int*   sci = (int*)(smb + CIB);

    const int tid = threadIdx.x;
    const int wid = tid >> 5;
    const int lid = tid & 31;
    const int y   = blockIdx.x;
    const int b   = blockIdx.y;
    const float* offm = g_offmod + (size_t)b * 27 * HWSZ;
    const float* __restrict__ xtb = g_xt + (size_t)b * HWSZ * CIN;

    // Phase 0: bilinear coord/weight tables (9 taps x 128 px)
    for (int i = tid; i < 1152; i += TBC) {
        int k = i >> 7;
        int p = i & 127;
        int lin = y * WW + p;
        float dy = offm[(2*k)   * HWSZ + lin];
        float dx = offm[(2*k+1) * HWSZ + lin];
        float m  = offm[(18+k)  * HWSZ + lin];
        float pyf = (float)(y + k / 3 - 1) + dy;
        float pxf = (float)(p + k % 3 - 1) + dx;
        float fy = floorf(pyf);
        float fx = floorf(pxf);
        float ty = pyf - fy;
        float tx = pxf - fx;
        int iy0 = (int)fy, ix0 = (int)fx;
        int iy1 = iy0 + 1, ix1 = ix0 + 1;
        float vy0 = (iy0 >= 0 && iy0 <= HH-1) ? 1.f : 0.f;
        float vy1 = (iy1 >= 0 && iy1 <= HH-1) ? 1.f : 0.f;
        float vx0 = (ix0 >= 0 && ix0 <= WW-1) ? 1.f : 0.f;
        float vx1 = (ix1 >= 0 && ix1 <= WW-1) ? 1.f : 0.f;
        int cy0 = min(max(iy0, 0), HH-1);
        int cy1 = min(max(iy1, 0), HH-1);
        int cx0 = min(max(ix0, 0), WW-1);
        int cx1 = min(max(ix1, 0), WW-1);
        scw[i       ] = (1.f - ty) * (1.f - tx) * m * vy0 * vx0;
        scw[1152 + i] = (1.f - ty) * tx         * m * vy0 * vx1;
        scw[2304 + i] = ty * (1.f - tx)         * m * vy1 * vx0;
        scw[3456 + i] = ty * tx                 * m * vy1 * vx1;
        sci[i       ] = cy0 * WW + cx0;
        sci[1152 + i] = cy0 * WW + cx1;
        sci[2304 + i] = cy1 * WW + cx0;
        sci[3456 + i] = cy1 * WW + cx1;
    }
    __syncthreads();

    // Lane maps
    const int warp_m = wid & 3;
    const int warp_n = wid >> 2;
    const uint32_t aoffl = (uint32_t)((lid & 15) * ROWB + (lid >> 4) * 16);
    const uint32_t boffl = (uint32_t)(((lid & 7) + ((lid >> 4) ? 8 : 0)) * ROWB + ((lid >> 3) & 1) * 16);
    const int chl = lid & 7;
    const int wpx = wid * 16 + (lid >> 3) * 4;   // base pixel for slots j=0..3

    float c[2][8][4];
    #pragma unroll
    for (int i = 0; i < 2; i++)
        #pragma unroll
        for (int j = 0; j < 8; j++)
            #pragma unroll
            for (int q = 0; q < 4; q++) c[i][j][q] = 0.f;

    // Prologue: fill stage 0 with chunk 0
    {
        wcopy_async(0, sb, tid);
        CPCOMMIT();
        char* sh = smb + 2 * MATB;
        char* sl = smb + 3 * MATB;
        Slot s;
        #pragma unroll
        for (int j = 0; j < 4; j++) {
            gather_slot(s, 0, wpx + j, xtb, chl, scw, sci);
            combine_slot(s, sh, sl, wpx + j, chl);
        }
        CPWAIT0();
        __syncthreads();
    }

    for (int t = 0; t < NCHUNK; t++) {
        const int s = t & 1;
        const int ns = s ^ 1;
        const uint32_t stg = sb + (uint32_t)(s * STAGEB);
        char* nsh = smb + ns * STAGEB + 2 * MATB;
        char* nsl = smb + ns * STAGEB + 3 * MATB;

        Slot s0, s1, s2, s3;
        const int u = t + 1;
        const int tap = u >> 1;
        const float* __restrict__ xq = xtb + ((u & 1) << 5);

        if (t < NCHUNK - 1) {
            wcopy_async(u, sb + (uint32_t)(ns * STAGEB), tid);
            CPCOMMIT();
            gather_slot(s0, tap, wpx + 0, xq, chl, scw, sci);
            gather_slot(s1, tap, wpx + 1, xq, chl, scw, sci);
        }

        do_kstep(stg, 0, warp_m, warp_n, aoffl, boffl, c);

        if (t < NCHUNK - 1) {
            gather_slot(s2, tap, wpx + 2, xq, chl, scw, sci);
            gather_slot(s3, tap, wpx + 3, xq, chl, scw, sci);
            combine_slot(s0, nsh, nsl, wpx + 0, chl);
            combine_slot(s1, nsh, nsl, wpx + 1, chl);
        }

        do_kstep(stg, 1, warp_m, warp_n, aoffl, boffl, c);

        if (t < NCHUNK - 1) {
            combine_slot(s2, nsh, nsl, wpx + 2, chl);
            combine_slot(s3, nsh, nsl, wpx + 3, chl);
        }

        CPWAIT0();
        __syncthreads();
    }

    // Epilogue: fragments -> global
    const int mrow = lid >> 2;
    const int ncol = (lid & 3) * 2;
    #pragma unroll
    for (int i = 0; i < 2; i++) {
        #pragma unroll
        for (int j = 0; j < 8; j++) {
            int m0 = warp_m * 32 + i * 16 + mrow;
            int n  = warp_n * 64 + j * 8 + ncol;
            float* p0 = out + ((size_t)(b * COUT + m0)) * HWSZ + y * WW + n;
            *(float2*)p0 = make_float2(c[i][j][0], c[i][j][1]);
            *(float2*)(p0 + 8 * HWSZ) = make_float2(c[i][j][2], c[i][j][3]);
        }
    }
}

// ---------------------------------------------------------------------------
extern "C" void kernel_launch(void* const* d_in, const int* in_sizes, int n_in,
                              void* d_out, int out_size)
{
    const float* x     = (const float*)d_in[0];
    const float* w_off = (const float*)d_in[1];
    const float* b_off = (const float*)d_in[2];
    const float* w_mod = (const float*)d_in[3];
    const float* b_mod = (const float*)d_in[4];
    const float* w_reg = (const float*)d_in[5];
    float* out = (float*)d_out;
    (void)in_sizes; (void)n_in; (void)out_size;

    const int smA = (XT + CIN * 9 * 28) * 4;
    cudaFuncSetAttribute(offmod_kernel, cudaFuncAttributeMaxDynamicSharedMemorySize, smA);
    cudaFuncSetAttribute(dcn_kernel,    cudaFuncAttributeMaxDynamicSharedMemorySize, SMEMB_TOTAL);

    wprep_kernel<<<(COUT * KTOT + 255) / 256, 256>>>(w_reg);

    dim3 gT(HWSZ / 64, NB);
    xt_kernel<<<gT, 256>>>(x);

    dim3 gA(WW / ATW, HH / ATH, NB);
    offmod_kernel<<<gA, 256, smA>>>(x, w_off, b_off, w_mod, b_mod);

    dim3 gB(HH, NB);
    dcn_kernel<<<gB, TBC, SMEMB_TOTAL>>>(out);
}

// round 9
// speedup vs baseline: 2.0694x; 1.0956x over previous
#include <cuda_runtime.h>
#include <cuda_bf16.h>
#include <cstdint>

#define HH 128
#define WW 128
#define HWSZ (HH*WW)
#define CIN 64
#define COUT 128
#define NB 4
#define KTOT 576      // CIN * 9
#define NCHUNK 18     // K chunks of 32

// ---------------- device scratch ----------------
__device__ float g_offmod[NB * 27 * HWSZ];              // offsets(18) + modulators(9)
__device__ float g_xt[NB * HWSZ * CIN];                 // x transposed: [b][hw][c]
__device__ __nv_bfloat16 g_wh[NCHUNK * 128 * 32];       // W hi  [chunk][oc][kl]
__device__ __nv_bfloat16 g_wl[NCHUNK * 128 * 32];       // W lo

__device__ __forceinline__ uint32_t smem_u32(const void* p) {
    uint32_t a;
    asm("{ .reg .u64 t; cvta.to.shared.u64 t, %1; cvt.u32.u64 %0, t; }" : "=r"(a) : "l"(p));
    return a;
}
__device__ __forceinline__ void ldm4(uint32_t* r, uint32_t addr) {
    asm volatile("ldmatrix.sync.aligned.m8n8.x4.shared.b16 {%0,%1,%2,%3}, [%4];"
                 : "=r"(r[0]), "=r"(r[1]), "=r"(r[2]), "=r"(r[3]) : "r"(addr));
}
__device__ __forceinline__ void mma_bf16(float* c, const uint32_t* a, const uint32_t* b) {
    asm volatile("mma.sync.aligned.m16n8k16.row.col.f32.bf16.bf16.f32 "
                 "{%0,%1,%2,%3}, {%4,%5,%6,%7}, {%8,%9}, {%0,%1,%2,%3};"
                 : "+f"(c[0]), "+f"(c[1]), "+f"(c[2]), "+f"(c[3])
                 : "r"(a[0]), "r"(a[1]), "r"(a[2]), "r"(a[3]), "r"(b[0]), "r"(b[1]));
}
__device__ __forceinline__ void cp16(uint32_t dst, const void* src) {
    asm volatile("cp.async.cg.shared.global [%0], [%1], 16;" :: "r"(dst), "l"(src));
}
#define CPCOMMIT() asm volatile("cp.async.commit_group;" ::: "memory")
#define CPWAIT0()  asm volatile("cp.async.wait_group 0;" ::: "memory")

// ---------------------------------------------------------------------------
// x transpose: [b][c][hw] -> [b][hw][c]
// ---------------------------------------------------------------------------
__global__ void xt_kernel(const float* __restrict__ x) {
    __shared__ float sm[64][65];
    const int tid = threadIdx.x;
    const int b   = blockIdx.y;
    const int hw0 = blockIdx.x * 64;
    const float* xb = x + (size_t)b * CIN * HWSZ;
    #pragma unroll
    for (int it = 0; it < 16; it++) {
        int c   = (tid >> 6) + it * 4;
        int hwl = tid & 63;
        sm[hwl][c] = xb[c * HWSZ + hw0 + hwl];
    }
    __syncthreads();
    float* xtb = g_xt + ((size_t)b * HWSZ + hw0) * CIN;
    #pragma unroll
    for (int it = 0; it < 16; it++) {
        int hwl = (tid >> 6) + it * 4;
        int cl  = tid & 63;
        xtb[hwl * CIN + cl] = sm[hwl][cl];
    }
}

// ---------------------------------------------------------------------------
// W prep: split into bf16 hi/lo, K reordered as k_new = tap*64 + c
// ---------------------------------------------------------------------------
__global__ void wprep_kernel(const float* __restrict__ w_reg) {
    int i = blockIdx.x * 256 + threadIdx.x;
    if (i >= COUT * KTOT) return;
    int oc = i / KTOT;
    int kn = i - oc * KTOT;
    int tap = kn >> 6;
    int c   = kn & 63;
    float v = w_reg[oc * KTOT + c * 9 + tap];
    __nv_bfloat16 h = __float2bfloat16_rn(v);
    float lo = v - __bfloat162float(h);
    int chunk = kn >> 5;
    int kl    = kn & 31;
    g_wh[(chunk * 128 + oc) * 32 + kl] = h;
    g_wl[(chunk * 128 + oc) * 32 + kl] = __float2bfloat16_rn(lo);
}

// ---------------------------------------------------------------------------
// Kernel A: fused offset + modulator 3x3 conv (SIMT fp32)
// ---------------------------------------------------------------------------
#define ATH 16
#define ATW 32
#define AHH 18
#define AHW 34
#define XT (CIN*AHH*AHW)

__global__ void __launch_bounds__(256, 1) offmod_kernel(
    const float* __restrict__ x,
    const float* __restrict__ w_off, const float* __restrict__ b_off,
    const float* __restrict__ w_mod, const float* __restrict__ b_mod)
{
    extern __shared__ float sm[];
    float* xs = sm;
    float* ws = sm + XT;

    const int tid = threadIdx.x;
    const int b   = blockIdx.z;
    const int ty0 = blockIdx.y * ATH;
    const int tx0 = blockIdx.x * ATW;
    const float* xb = x + (size_t)b * CIN * HWSZ;

    for (int i = tid; i < XT; i += 256) {
        int c  = i / (AHH*AHW);
        int r  = i - c * (AHH*AHW);
        int yy = r / AHW;
        int xx = r - yy * AHW;
        int gy = ty0 + yy - 1;
        int gx = tx0 + xx - 1;
        float v = 0.f;
        if (gy >= 0 && gy < HH && gx >= 0 && gx < WW)
            v = xb[c * HWSZ + gy * WW + gx];
        xs[i] = v;
    }
    for (int i = tid; i < CIN*9*27; i += 256) {
        int o  = i % 27;
        int ck = i / 27;
        int c  = ck / 9;
        int k  = ck - c * 9;
        float v = (o < 18) ? w_off[(o * CIN + c) * 9 + k]
                           : w_mod[((o - 18) * CIN + c) * 9 + k];
        ws[ck * 28 + o] = v;
    }
    __syncthreads();

    const int px = tid & 31;
    const int py = tid >> 5;

    float acc0[27], acc1[27];
    #pragma unroll
    for (int o = 0; o < 27; o++) { acc0[o] = 0.f; acc1[o] = 0.f; }

    for (int c = 0; c < CIN; c++) {
        const float* xc = xs + c * (AHH*AHW);
        #pragma unroll
        for (int ky = 0; ky < 3; ky++) {
            #pragma unroll
            for (int kx = 0; kx < 3; kx++) {
                float xv0 = xc[(py + ky) * AHW + px + kx];
                float xv1 = xc[(py + 8 + ky) * AHW + px + kx];
                const float4* wp = (const float4*)(ws + (c * 9 + ky * 3 + kx) * 28);
                #pragma unroll
                for (int q = 0; q < 7; q++) {
                    float4 t = wp[q];
                    const int o = 4 * q;
                    acc0[o+0] += t.x * xv0;  acc1[o+0] += t.x * xv1;
                    if (o + 1 < 27) { acc0[o+1] += t.y * xv0;  acc1[o+1] += t.y * xv1; }
                    if (o + 2 < 27) { acc0[o+2] += t.z * xv0;  acc1[o+2] += t.z * xv1; }
                    if (o + 3 < 27) { acc0[o+3] += t.w * xv0;  acc1[o+3] += t.w * xv1; }
                }
            }
        }
    }

    const int gy = ty0 + py;
    const int gx = tx0 + px;
    float* outp = g_offmod + (size_t)b * 27 * HWSZ;
    #pragma unroll
    for (int o = 0; o < 27; o++) {
        float bias = (o < 18) ? b_off[o] : b_mod[o - 18];
        float v0 = acc0[o] + bias;
        float v1 = acc1[o] + bias;
        if (o >= 18) {
            v0 = 2.f / (1.f + __expf(-v0));
            v1 = 2.f / (1.f + __expf(-v1));
        }
        outp[o * HWSZ + gy * WW + gx]       = v0;
        outp[o * HWSZ + (gy + 8) * WW + gx] = v1;
    }
}

// ---------------------------------------------------------------------------
// Kernel B: homogeneous software-pipelined bf16 mma GEMM + sampling.
// 512 threads (16 warps), each warp a 32x32 output tile + 2 gather slots.
// 4 warps per SMSP for latency hiding; launch_bounds caps regs at 128.
// ---------------------------------------------------------------------------
#define TBC 512
#define ROWB 80                 // smem row stride bytes (conflict-free for ldmatrix)
#define MATB (128 * ROWB)       // 10240
#define STAGEB (4 * MATB)       // 40960: Whi | Wlo | Shi | Slo
#define CWB (2 * STAGEB)        // 81920
#define CIB (CWB + 4 * 1152 * 4)
#define SMEMB_TOTAL (CIB + 4 * 1152 * 4)   // 118784

struct Slot {
    float4 a[4];
    float  w[4];
};

__device__ __forceinline__ void gather_slot(Slot& s, int tap, int px, const float* __restrict__ xq,
                                            int chl, const float* scw, const int* sci) {
    int idx = tap * 128 + px;
    s.w[0] = scw[idx]; s.w[1] = scw[idx+1152]; s.w[2] = scw[idx+2304]; s.w[3] = scw[idx+3456];
    int i0 = sci[idx], i1 = sci[idx+1152], i2 = sci[idx+2304], i3 = sci[idx+3456];
    s.a[0] = *(const float4*)(xq + (size_t)i0 * CIN + chl * 4);
    s.a[1] = *(const float4*)(xq + (size_t)i1 * CIN + chl * 4);
    s.a[2] = *(const float4*)(xq + (size_t)i2 * CIN + chl * 4);
    s.a[3] = *(const float4*)(xq + (size_t)i3 * CIN + chl * 4);
}

__device__ __forceinline__ void combine_slot(const Slot& s, char* sh, char* sl, int px, int chl) {
    float v0 = s.w[0]*s.a[0].x + s.w[1]*s.a[1].x + s.w[2]*s.a[2].x + s.w[3]*s.a[3].x;
    float v1 = s.w[0]*s.a[0].y + s.w[1]*s.a[1].y + s.w[2]*s.a[2].y + s.w[3]*s.a[3].y;
    float v2 = s.w[0]*s.a[0].z + s.w[1]*s.a[1].z + s.w[2]*s.a[2].z + s.w[3]*s.a[3].z;
    float v3 = s.w[0]*s.a[0].w + s.w[1]*s.a[1].w + s.w[2]*s.a[2].w + s.w[3]*s.a[3].w;
    __nv_bfloat16 h0 = __float2bfloat16_rn(v0);
    __nv_bfloat16 h1 = __float2bfloat16_rn(v1);
    __nv_bfloat16 h2 = __float2bfloat16_rn(v2);
    __nv_bfloat16 h3 = __float2bfloat16_rn(v3);
    __nv_bfloat16 l0 = __float2bfloat16_rn(v0 - __bfloat162float(h0));
    __nv_bfloat16 l1 = __float2bfloat16_rn(v1 - __bfloat162float(h1));
    __nv_bfloat16 l2 = __float2bfloat16_rn(v2 - __bfloat162float(h2));
    __nv_bfloat16 l3 = __float2bfloat16_rn(v3 - __bfloat162float(h3));
    uint32_t hp0 = (uint32_t)__bfloat16_as_ushort(h0) | ((uint32_t)__bfloat16_as_ushort(h1) << 16);
    uint32_t hp1 = (uint32_t)__bfloat16_as_ushort(h2) | ((uint32_t)__bfloat16_as_ushort(h3) << 16);
    uint32_t lp0 = (uint32_t)__bfloat16_as_ushort(l0) | ((uint32_t)__bfloat16_as_ushort(l1) << 16);
    uint32_t lp1 = (uint32_t)__bfloat16_as_ushort(l2) | ((uint32_t)__bfloat16_as_ushort(l3) << 16);
    *(uint2*)(sh + px * ROWB + chl * 8) = make_uint2(hp0, hp1);
    *(uint2*)(sl + px * ROWB + chl * 8) = make_uint2(lp0, lp1);
}

__device__ __forceinline__ void wcopy_async(int chunk, uint32_t stg, int tid) {
    const char* srcH = (const char*)g_wh + (size_t)chunk * 128 * 64;
    const char* srcL = (const char*)g_wl + (size_t)chunk * 128 * 64;
    #pragma unroll
    for (int it = 0; it < 2; it++) {
        int i = tid + it * TBC;     // 0..1023
        int mat = i >> 9;
        int rr  = (i >> 2) & 127;
        int c4  = i & 3;
        const char* src = (mat ? srcL : srcH) + rr * 64 + c4 * 16;
        cp16(stg + (uint32_t)(mat * MATB + rr * ROWB + c4 * 16), src);
    }
}

__device__ __forceinline__ void do_kstep(uint32_t stg, int ks, int warp_m, int warp_n,
                                         uint32_t aoffl, uint32_t boffl, float c[2][4][4]) {
    const uint32_t abase = stg + (uint32_t)(warp_m * 32 * ROWB + ks * 32) + aoffl;
    uint32_t ah[2][4], al[2][4];
    ldm4(ah[0], abase);
    ldm4(ah[1], abase + 16 * ROWB);
    ldm4(al[0], abase + MATB);
    ldm4(al[1], abase + MATB + 16 * ROWB);
    const uint32_t bbase = stg + (uint32_t)(2 * MATB + warp_n * 32 * ROWB + ks * 32) + boffl;
    uint32_t bh[4][2], bl[4][2];
    #pragma unroll
    for (int jj = 0; jj < 2; jj++) {
        uint32_t tmp[4];
        ldm4(tmp, bbase + (uint32_t)(jj * 16 * ROWB));
        bh[2*jj][0] = tmp[0]; bh[2*jj][1] = tmp[1];
        bh[2*jj+1][0] = tmp[2]; bh[2*jj+1][1] = tmp[3];
        ldm4(tmp, bbase + (uint32_t)(MATB + jj * 16 * ROWB));
        bl[2*jj][0] = tmp[0]; bl[2*jj][1] = tmp[1];
        bl[2*jj+1][0] = tmp[2]; bl[2*jj+1][1] = tmp[3];
    }
    #pragma unroll
    for (int i = 0; i < 2; i++) {
        #pragma unroll
        for (int j = 0; j < 4; j++) {
            mma_bf16(c[i][j], ah[i], bh[j]);
            mma_bf16(c[i][j], ah[i], bl[j]);
            mma_bf16(c[i][j], al[i], bh[j]);
        }
    }
}

__global__ void __launch_bounds__(TBC, 1) dcn_kernel(float* __restrict__ out)
{
    extern __shared__ char smb[];
    const uint32_t sb = smem_u32(smb);
    float* scw = (float*)(smb + CWB);
    int*   sci = (int*)(smb + CIB);

    const int tid = threadIdx.x;
    const int wid = tid >> 5;
    const int lid = tid & 31;
    const int y   = blockIdx.x;
    const int b   = blockIdx.y;
    const float* offm = g_offmod + (size_t)b * 27 * HWSZ;
    const float* __restrict__ xtb = g_xt + (size_t)b * HWSZ * CIN;

    // Phase 0: bilinear coord/weight tables (9 taps x 128 px)
    for (int i = tid; i < 1152; i += TBC) {
        int k = i >> 7;
        int p = i & 127;
        int lin = y * WW + p;
        float dy = offm[(2*k)   * HWSZ + lin];
        float dx = offm[(2*k+1) * HWSZ + lin];
        float m  = offm[(18+k)  * HWSZ + lin];
        float pyf = (float)(y + k / 3 - 1) + dy;
        float pxf = (float)(p + k % 3 - 1) + dx;
        float fy = floorf(pyf);
        float fx = floorf(pxf);
        float ty = pyf - fy;
        float tx = pxf - fx;
        int iy0 = (int)fy, ix0 = (int)fx;
        int iy1 = iy0 + 1, ix1 = ix0 + 1;
        float vy0 = (iy0 >= 0 && iy0 <= HH-1) ? 1.f : 0.f;
        float vy1 = (iy1 >= 0 && iy1 <= HH-1) ? 1.f : 0.f;
        float vx0 = (ix0 >= 0 && ix0 <= WW-1) ? 1.f : 0.f;
        float vx1 = (ix1 >= 0 && ix1 <= WW-1) ? 1.f : 0.f;
        int cy0 = min(max(iy0, 0), HH-1);
        int cy1 = min(max(iy1, 0), HH-1);
        int cx0 = min(max(ix0, 0), WW-1);
        int cx1 = min(max(ix1, 0), WW-1);
        scw[i       ] = (1.f - ty) * (1.f - tx) * m * vy0 * vx0;
        scw[1152 + i] = (1.f - ty) * tx         * m * vy0 * vx1;
        scw[2304 + i] = ty * (1.f - tx)         * m * vy1 * vx0;
        scw[3456 + i] = ty * tx                 * m * vy1 * vx1;
        sci[i       ] = cy0 * WW + cx0;
        sci[1152 + i] = cy0 * WW + cx1;
        sci[2304 + i] = cy1 * WW + cx0;
        sci[3456 + i] = cy1 * WW + cx1;
    }
    __syncthreads();

    // Lane maps
    const int warp_m = wid & 3;      // oc tile of 32
    const int warp_n = wid >> 2;     // px tile of 32
    const uint32_t aoffl = (uint32_t)((lid & 15) * ROWB + (lid >> 4) * 16);
    const uint32_t boffl = (uint32_t)(((lid & 7) + ((lid >> 4) ? 8 : 0)) * ROWB + ((lid >> 3) & 1) * 16);
    const int chl = lid & 7;
    const int wpx = wid * 8 + (lid >> 3);   // slot j pixel: wpx + j*4

    float c[2][4][4];
    #pragma unroll
    for (int i = 0; i < 2; i++)
        #pragma unroll
        for (int j = 0; j < 4; j++)
            #pragma unroll
            for (int q = 0; q < 4; q++) c[i][j][q] = 0.f;

    // Prologue: fill stage 0 with chunk 0
    {
        wcopy_async(0, sb, tid);
        CPCOMMIT();
        char* sh = smb + 2 * MATB;
        char* sl = smb + 3 * MATB;
        Slot s;
        #pragma unroll
        for (int j = 0; j < 2; j++) {
            gather_slot(s, 0, wpx + j * 4, xtb, chl, scw, sci);
            combine_slot(s, sh, sl, wpx + j * 4, chl);
        }
        CPWAIT0();
        __syncthreads();
    }

    for (int t = 0; t < NCHUNK; t++) {
        const int s = t & 1;
        const int ns = s ^ 1;
        const uint32_t stg = sb + (uint32_t)(s * STAGEB);
        char* nsh = smb + ns * STAGEB + 2 * MATB;
        char* nsl = smb + ns * STAGEB + 3 * MATB;

        Slot s0, s1;
        const int u = t + 1;
        const int tap = u >> 1;
        const float* __restrict__ xq = xtb + ((u & 1) << 5);

        if (t < NCHUNK - 1) {
            wcopy_async(u, sb + (uint32_t)(ns * STAGEB), tid);
            CPCOMMIT();
            gather_slot(s0, tap, wpx + 0, xq, chl, scw, sci);
            gather_slot(s1, tap, wpx + 4, xq, chl, scw, sci);
        }

        do_kstep(stg, 0, warp_m, warp_n, aoffl, boffl, c);

        if (t < NCHUNK - 1) {
            combine_slot(s0, nsh, nsl, wpx + 0, chl);
            combine_slot(s1, nsh, nsl, wpx + 4, chl);
        }

        do_kstep(stg, 1, warp_m, warp_n, aoffl, boffl, c);

        CPWAIT0();
        __syncthreads();
    }

    // Epilogue: fragments -> global
    const int mrow = lid >> 2;
    const int ncol = (lid & 3) * 2;
    #pragma unroll
    for (int i = 0; i < 2; i++) {
        #pragma unroll
        for (int j = 0; j < 4; j++) {
            int m0 = warp_m * 32 + i * 16 + mrow;
            int n  = warp_n * 32 + j * 8 + ncol;
            float* p0 = out + ((size_t)(b * COUT + m0)) * HWSZ + y * WW + n;
            *(float2*)p0 = make_float2(c[i][j][0], c[i][j][1]);
            *(float2*)(p0 + 8 * HWSZ) = make_float2(c[i][j][2], c[i][j][3]);
        }
    }
}

// ---------------------------------------------------------------------------
extern "C" void kernel_launch(void* const* d_in, const int* in_sizes, int n_in,
                              void* d_out, int out_size)
{
    const float* x     = (const float*)d_in[0];
    const float* w_off = (const float*)d_in[1];
    const float* b_off = (const float*)d_in[2];
    const float* w_mod = (const float*)d_in[3];
    const float* b_mod = (const float*)d_in[4];
    const float* w_reg = (const float*)d_in[5];
    float* out = (float*)d_out;
    (void)in_sizes; (void)n_in; (void)out_size;

    const int smA = (XT + CIN * 9 * 28) * 4;
    cudaFuncSetAttribute(offmod_kernel, cudaFuncAttributeMaxDynamicSharedMemorySize, smA);
    cudaFuncSetAttribute(dcn_kernel,    cudaFuncAttributeMaxDynamicSharedMemorySize, SMEMB_TOTAL);

    wprep_kernel<<<(COUT * KTOT + 255) / 256, 256>>>(w_reg);

    dim3 gT(HWSZ / 64, NB);
    xt_kernel<<<gT, 256>>>(x);

    dim3 gA(WW / ATW, HH / ATH, NB);
    offmod_kernel<<<gA, 256, smA>>>(x, w_off, b_off, w_mod, b_mod);

    dim3 gB(HH, NB);
    dcn_kernel<<<gB, TBC, SMEMB_TOTAL>>>(out);
}

// round 11
// speedup vs baseline: 2.1278x; 1.0282x over previous
#include <cuda_runtime.h>
#include <cuda_bf16.h>
#include <cstdint>

#define HH 128
#define WW 128
#define HWSZ (HH*WW)
#define CIN 64
#define COUT 128
#define NB 4
#define KTOT 576      // CIN * 9
#define NCHUNK 18     // K chunks of 32

// ---------------- device scratch ----------------
__device__ float g_offmod[NB * 27 * HWSZ];              // offsets(18) + modulators(9)
__device__ float g_xt[NB * HWSZ * CIN];                 // x transposed: [b][hw][c]
__device__ __nv_bfloat16 g_wh[NCHUNK * 128 * 32];       // W hi  [chunk][oc][kl]
__device__ __nv_bfloat16 g_wl[NCHUNK * 128 * 32];       // W lo

__device__ __forceinline__ uint32_t smem_u32(const void* p) {
    uint32_t a;
    asm("{ .reg .u64 t; cvta.to.shared.u64 t, %1; cvt.u32.u64 %0, t; }" : "=r"(a) : "l"(p));
    return a;
}
__device__ __forceinline__ void ldm4(uint32_t* r, uint32_t addr) {
    asm volatile("ldmatrix.sync.aligned.m8n8.x4.shared.b16 {%0,%1,%2,%3}, [%4];"
                 : "=r"(r[0]), "=r"(r[1]), "=r"(r[2]), "=r"(r[3]) : "r"(addr));
}
__device__ __forceinline__ void mma_bf16(float* c, const uint32_t* a, const uint32_t* b) {
    asm volatile("mma.sync.aligned.m16n8k16.row.col.f32.bf16.bf16.f32 "
                 "{%0,%1,%2,%3}, {%4,%5,%6,%7}, {%8,%9}, {%0,%1,%2,%3};"
                 : "+f"(c[0]), "+f"(c[1]), "+f"(c[2]), "+f"(c[3])
                 : "r"(a[0]), "r"(a[1]), "r"(a[2]), "r"(a[3]), "r"(b[0]), "r"(b[1]));
}
__device__ __forceinline__ void cp16(uint32_t dst, const void* src) {
    asm volatile("cp.async.cg.shared.global [%0], [%1], 16;" :: "r"(dst), "l"(src));
}
#define CPCOMMIT() asm volatile("cp.async.commit_group;" ::: "memory")
#define CPWAIT0()  asm volatile("cp.async.wait_group 0;" ::: "memory")

// ---------------------------------------------------------------------------
// x transpose: [b][c][hw] -> [b][hw][c]
// ---------------------------------------------------------------------------
__global__ void xt_kernel(const float* __restrict__ x) {
    __shared__ float sm[64][65];
    const int tid = threadIdx.x;
    const int b   = blockIdx.y;
    const int hw0 = blockIdx.x * 64;
    const float* xb = x + (size_t)b * CIN * HWSZ;
    #pragma unroll
    for (int it = 0; it < 16; it++) {
        int c   = (tid >> 6) + it * 4;
        int hwl = tid & 63;
        sm[hwl][c] = xb[c * HWSZ + hw0 + hwl];
    }
    __syncthreads();
    float* xtb = g_xt + ((size_t)b * HWSZ + hw0) * CIN;
    #pragma unroll
    for (int it = 0; it < 16; it++) {
        int hwl = (tid >> 6) + it * 4;
        int cl  = tid & 63;
        xtb[hwl * CIN + cl] = sm[hwl][cl];
    }
}

// ---------------------------------------------------------------------------
// W prep: split into bf16 hi/lo, K reordered as k_new = tap*64 + c
// ---------------------------------------------------------------------------
__global__ void wprep_kernel(const float* __restrict__ w_reg) {
    int i = blockIdx.x * 256 + threadIdx.x;
    if (i >= COUT * KTOT) return;
    int oc = i / KTOT;
    int kn = i - oc * KTOT;
    int tap = kn >> 6;
    int c   = kn & 63;
    float v = w_reg[oc * KTOT + c * 9 + tap];
    __nv_bfloat16 h = __float2bfloat16_rn(v);
    float lo = v - __bfloat162float(h);
    int chunk = kn >> 5;
    int kl    = kn & 31;
    g_wh[(chunk * 128 + oc) * 32 + kl] = h;
    g_wl[(chunk * 128 + oc) * 32 + kl] = __float2bfloat16_rn(lo);
}

// ---------------------------------------------------------------------------
// Kernel A: fused offset + modulator 3x3 conv (SIMT fp32)
// ---------------------------------------------------------------------------
#define ATH 16
#define ATW 32
#define AHH 18
#define AHW 34
#define XT (CIN*AHH*AHW)

__global__ void __launch_bounds__(256, 1) offmod_kernel(
    const float* __restrict__ x,
    const float* __restrict__ w_off, const float* __restrict__ b_off,
    const float* __restrict__ w_mod, const float* __restrict__ b_mod)
{
    extern __shared__ float sm[];
    float* xs = sm;
    float* ws = sm + XT;

    const int tid = threadIdx.x;
    const int b   = blockIdx.z;
    const int ty0 = blockIdx.y * ATH;
    const int tx0 = blockIdx.x * ATW;
    const float* xb = x + (size_t)b * CIN * HWSZ;

    for (int i = tid; i < XT; i += 256) {
        int c  = i / (AHH*AHW);
        int r  = i - c * (AHH*AHW);
        int yy = r / AHW;
        int xx = r - yy * AHW;
        int gy = ty0 + yy - 1;
        int gx = tx0 + xx - 1;
        float v = 0.f;
        if (gy >= 0 && gy < HH && gx >= 0 && gx < WW)
            v = xb[c * HWSZ + gy * WW + gx];
        xs[i] = v;
    }
    for (int i = tid; i < CIN*9*27; i += 256) {
        int o  = i % 27;
        int ck = i / 27;
        int c  = ck / 9;
        int k  = ck - c * 9;
        float v = (o < 18) ? w_off[(o * CIN + c) * 9 + k]
                           : w_mod[((o - 18) * CIN + c) * 9 + k];
        ws[ck * 28 + o] = v;
    }
    __syncthreads();

    const int px = tid & 31;
    const int py = tid >> 5;

    float acc0[27], acc1[27];
    #pragma unroll
    for (int o = 0; o < 27; o++) { acc0[o] = 0.f; acc1[o] = 0.f; }

    for (int c = 0; c < CIN; c++) {
        const float* xc = xs + c * (AHH*AHW);
        #pragma unroll
        for (int ky = 0; ky < 3; ky++) {
            #pragma unroll
            for (int kx = 0; kx < 3; kx++) {
                float xv0 = xc[(py + ky) * AHW + px + kx];
                float xv1 = xc[(py + 8 + ky) * AHW + px + kx];
                const float4* wp = (const float4*)(ws + (c * 9 + ky * 3 + kx) * 28);
                #pragma unroll
                for (int q = 0; q < 7; q++) {
                    float4 t = wp[q];
                    const int o = 4 * q;
                    acc0[o+0] += t.x * xv0;  acc1[o+0] += t.x * xv1;
                    if (o + 1 < 27) { acc0[o+1] += t.y * xv0;  acc1[o+1] += t.y * xv1; }
                    if (o + 2 < 27) { acc0[o+2] += t.z * xv0;  acc1[o+2] += t.z * xv1; }
                    if (o + 3 < 27) { acc0[o+3] += t.w * xv0;  acc1[o+3] += t.w * xv1; }
                }
            }
        }
    }

    const int gy = ty0 + py;
    const int gx = tx0 + px;
    float* outp = g_offmod + (size_t)b * 27 * HWSZ;
    #pragma unroll
    for (int o = 0; o < 27; o++) {
        float bias = (o < 18) ? b_off[o] : b_mod[o - 18];
        float v0 = acc0[o] + bias;
        float v1 = acc1[o] + bias;
        if (o >= 18) {
            v0 = 2.f / (1.f + __expf(-v0));
            v1 = 2.f / (1.f + __expf(-v1));
        }
        outp[o * HWSZ + gy * WW + gx]       = v0;
        outp[o * HWSZ + (gy + 8) * WW + gx] = v1;
    }
}

// ---------------------------------------------------------------------------
// Kernel B: homogeneous software-pipelined bf16 mma GEMM + sampling.
// Block = 128 oc x 64 px (half row), 256 threads / 8 warps, each warp a
// 32x32 tile + 2 gather slots. 2 CTAs per SM (launch_bounds(256,2)) so
// barrier drains in one CTA overlap with issue in the other.
// ---------------------------------------------------------------------------
#define TBC 256
#define NPX 64                  // pixels per block
#define ROWB 80                 // smem row stride bytes (conflict-free for ldmatrix)
#define WMATB (128 * ROWB)      // 10240: one W matrix (hi or lo)
#define SMATB (NPX * ROWB)      // 5120:  one S matrix (hi or lo)
#define STAGEB (2 * WMATB + 2 * SMATB)   // 30720: Whi | Wlo | Shi | Slo
#define SOFF   (2 * WMATB)      // S hi offset within stage
#define CWB (2 * STAGEB)        // 61440
#define NTAB (9 * NPX)          // 576 table entries
#define CIB (CWB + 4 * NTAB * 4)
#define SMEMB_TOTAL (CIB + 4 * NTAB * 4)   // 79872

struct Slot {
    float4 a[4];
    float  w[4];
};

__device__ __forceinline__ void gather_slot(Slot& s, int tap, int px, const float* __restrict__ xq,
                                            int chl, const float* scw, const int* sci) {
    int idx = tap * NPX + px;
    s.w[0] = scw[idx]; s.w[1] = scw[idx+NTAB]; s.w[2] = scw[idx+2*NTAB]; s.w[3] = scw[idx+3*NTAB];
    int i0 = sci[idx], i1 = sci[idx+NTAB], i2 = sci[idx+2*NTAB], i3 = sci[idx+3*NTAB];
    s.a[0] = *(const float4*)(xq + (size_t)i0 * CIN + chl * 4);
    s.a[1] = *(const float4*)(xq + (size_t)i1 * CIN + chl * 4);
    s.a[2] = *(const float4*)(xq + (size_t)i2 * CIN + chl * 4);
    s.a[3] = *(const float4*)(xq + (size_t)i3 * CIN + chl * 4);
}

__device__ __forceinline__ void combine_slot(const Slot& s, char* sh, char* sl, int px, int chl) {
    float v0 = s.w[0]*s.a[0].x + s.w[1]*s.a[1].x + s.w[2]*s.a[2].x + s.w[3]*s.a[3].x;
    float v1 = s.w[0]*s.a[0].y + s.w[1]*s.a[1].y + s.w[2]*s.a[2].y + s.w[3]*s.a[3].y;
    float v2 = s.w[0]*s.a[0].z + s.w[1]*s.a[1].z + s.w[2]*s.a[2].z + s.w[3]*s.a[3].z;
    float v3 = s.w[0]*s.a[0].w + s.w[1]*s.a[1].w + s.w[2]*s.a[2].w + s.w[3]*s.a[3].w;
    __nv_bfloat16 h0 = __float2bfloat16_rn(v0);
    __nv_bfloat16 h1 = __float2bfloat16_rn(v1);
    __nv_bfloat16 h2 = __float2bfloat16_rn(v2);
    __nv_bfloat16 h3 = __float2bfloat16_rn(v3);
    __nv_bfloat16 l0 = __float2bfloat16_rn(v0 - __bfloat162float(h0));
    __nv_bfloat16 l1 = __float2bfloat16_rn(v1 - __bfloat162float(h1));
    __nv_bfloat16 l2 = __float2bfloat16_rn(v2 - __bfloat162float(h2));
    __nv_bfloat16 l3 = __float2bfloat16_rn(v3 - __bfloat162float(h3));
    uint32_t hp0 = (uint32_t)__bfloat16_as_ushort(h0) | ((uint32_t)__bfloat16_as_ushort(h1) << 16);
    uint32_t hp1 = (uint32_t)__bfloat16_as_ushort(h2) | ((uint32_t)__bfloat16_as_ushort(h3) << 16);
    uint32_t lp0 = (uint32_t)__bfloat16_as_ushort(l0) | ((uint32_t)__bfloat16_as_ushort(l1) << 16);
    uint32_t lp1 = (uint32_t)__bfloat16_as_ushort(l2) | ((uint32_t)__bfloat16_as_ushort(l3) << 16);
    *(uint2*)(sh + px * ROWB + chl * 8) = make_uint2(hp0, hp1);
    *(uint2*)(sl + px * ROWB + chl * 8) = make_uint2(lp0, lp1);
}

__device__ __forceinline__ void wcopy_async(int chunk, uint32_t stg, int tid) {
    const char* srcH = (const char*)g_wh + (size_t)chunk * 128 * 64;
    const char* srcL = (const char*)g_wl + (size_t)chunk * 128 * 64;
    #pragma unroll
    for (int it = 0; it < 4; it++) {
        int i = tid + it * TBC;     // 0..1023
        int mat = i >> 9;
        int rr  = (i >> 2) & 127;
        int c4  = i & 3;
        const char* src = (mat ? srcL : srcH) + rr * 64 + c4 * 16;
        cp16(stg + (uint32_t)(mat * WMATB + rr * ROWB + c4 * 16), src);
    }
}

__device__ __forceinline__ void do_kstep(uint32_t stg, int ks, int warp_m, int warp_n,
                                         uint32_t aoffl, uint32_t boffl, float c[2][4][4]) {
    const uint32_t abase = stg + (uint32_t)(warp_m * 32 * ROWB + ks * 32) + aoffl;
    uint32_t ah[2][4], al[2][4];
    ldm4(ah[0], abase);
    ldm4(ah[1], abase + 16 * ROWB);
    ldm4(al[0], abase + WMATB);
    ldm4(al[1], abase + WMATB + 16 * ROWB);
    const uint32_t bbase = stg + (uint32_t)(SOFF + warp_n * 32 * ROWB + ks * 32) + boffl;
    uint32_t bh[4][2], bl[4][2];
    #pragma unroll
    for (int jj = 0; jj < 2; jj++) {
        uint32_t tmp[4];
        ldm4(tmp, bbase + (uint32_t)(jj * 16 * ROWB));
        bh[2*jj][0] = tmp[0]; bh[2*jj][1] = tmp[1];
        bh[2*jj+1][0] = tmp[2]; bh[2*jj+1][1] = tmp[3];
        ldm4(tmp, bbase + (uint32_t)(SMATB + jj * 16 * ROWB));
        bl[2*jj][0] = tmp[0]; bl[2*jj][1] = tmp[1];
        bl[2*jj+1][0] = tmp[2]; bl[2*jj+1][1] = tmp[3];
    }
    #pragma unroll
    for (int i = 0; i < 2; i++) {
        #pragma unroll
        for (int j = 0; j < 4; j++) {
            mma_bf16(c[i][j], ah[i], bh[j]);
            mma_bf16(c[i][j], ah[i], bl[j]);
            mma_bf16(c[i][j], al[i], bh[j]);
        }
    }
}

__global__ void __launch_bounds__(TBC, 2) dcn_kernel(float* __restrict__ out)
{
    extern __shared__ char smb[];
    const uint32_t sb = smem_u32(smb);
    float* scw = (float*)(smb + CWB);
    int*   sci = (int*)(smb + CIB);

    const int tid  = threadIdx.x;
    const int wid  = tid >> 5;
    const int lid  = tid & 31;
    const int half = blockIdx.x;          // 0/1: pixel half of the row
    const int y    = blockIdx.y;
    const int b    = blockIdx.z;
    const int px0  = half * NPX;
    const float* offm = g_offmod + (size_t)b * 27 * HWSZ;
    const float* __restrict__ xtb = g_xt + (size_t)b * HWSZ * CIN;

    // Phase 0: bilinear coord/weight tables (9 taps x 64 px)
    for (int i = tid; i < NTAB; i += TBC) {
        int k = i / NPX;
        int p = i - k * NPX;
        int gx = px0 + p;
        int lin = y * WW + gx;
        float dy = offm[(2*k)   * HWSZ + lin];
        float dx = offm[(2*k+1) * HWSZ + lin];
        float m  = offm[(18+k)  * HWSZ + lin];
        float pyf = (float)(y  + k / 3 - 1) + dy;
        float pxf = (float)(gx + k % 3 - 1) + dx;
        float fy = floorf(pyf);
        float fx = floorf(pxf);
        float ty = pyf - fy;
        float tx = pxf - fx;
        int iy0 = (int)fy, ix0 = (int)fx;
        int iy1 = iy0 + 1, ix1 = ix0 + 1;
        float vy0 = (iy0 >= 0 && iy0 <= HH-1) ? 1.f : 0.f;
        float vy1 = (iy1 >= 0 && iy1 <= HH-1) ? 1.f : 0.f;
        float vx0 = (ix0 >= 0 && ix0 <= WW-1) ? 1.f : 0.f;
        float vx1 = (ix1 >= 0 && ix1 <= WW-1) ? 1.f : 0.f;
        int cy0 = min(max(iy0, 0), HH-1);
        int cy1 = min(max(iy1, 0), HH-1);
        int cx0 = min(max(ix0, 0), WW-1);
        int cx1 = min(max(ix1, 0), WW-1);
        scw[i         ] = (1.f - ty) * (1.f - tx) * m * vy0 * vx0;
        scw[NTAB   + i] = (1.f - ty) * tx         * m * vy0 * vx1;
        scw[2*NTAB + i] = ty * (1.f - tx)         * m * vy1 * vx0;
        scw[3*NTAB + i] = ty * tx                 * m * vy1 * vx1;
        sci[i         ] = cy0 * WW + cx0;
        sci[NTAB   + i] = cy0 * WW + cx1;
        sci[2*NTAB + i] = cy1 * WW + cx0;
        sci[3*NTAB + i] = cy1 * WW + cx1;
    }
    __syncthreads();

    // Lane maps
    const int warp_m = wid & 3;      // oc tile of 32
    const int warp_n = wid >> 2;     // px tile of 32 (0/1)
    const uint32_t aoffl = (uint32_t)((lid & 15) * ROWB + (lid >> 4) * 16);
    const uint32_t boffl = (uint32_t)(((lid & 7) + ((lid >> 4) ? 8 : 0)) * ROWB + ((lid >> 3) & 1) * 16);
    const int chl = lid & 7;
    const int wpx = wid * 8 + (lid >> 3);   // slot j pixel (local): wpx + j*4

    float c[2][4][4];
    #pragma unroll
    for (int i = 0; i < 2; i++)
        #pragma unroll
        for (int j = 0; j < 4; j++)
            #pragma unroll
            for (int q = 0; q < 4; q++) c[i][j][q] = 0.f;

    // Prologue: fill stage 0 with chunk 0
    {
        wcopy_async(0, sb, tid);
        CPCOMMIT();
        char* sh = smb + SOFF;
        char* sl = smb + SOFF + SMATB;
        Slot s;
        #pragma unroll
        for (int j = 0; j < 2; j++) {
            gather_slot(s, 0, wpx + j * 4, xtb, chl, scw, sci);
            combine_slot(s, sh, sl, wpx + j * 4, chl);
        }
        CPWAIT0();
        __syncthreads();
    }

    for (int t = 0; t < NCHUNK; t++) {
        const int s = t & 1;
        const int ns = s ^ 1;
        const uint32_t stg = sb + (uint32_t)(s * STAGEB);
        char* nsh = smb + ns * STAGEB + SOFF;
        char* nsl = smb + ns * STAGEB + SOFF + SMATB;

        Slot s0, s1;
        const int u = t + 1;
        const int tap = u >> 1;
        const float* __restrict__ xq = xtb + ((u & 1) << 5);

        if (t < NCHUNK - 1) {
            wcopy_async(u, sb + (uint32_t)(ns * STAGEB), tid);
            CPCOMMIT();
            gather_slot(s0, tap, wpx + 0, xq, chl, scw, sci);
            gather_slot(s1, tap, wpx + 4, xq, chl, scw, sci);
        }

        do_kstep(stg, 0, warp_m, warp_n, aoffl, boffl, c);

        if (t < NCHUNK - 1) {
            combine_slot(s0, nsh, nsl, wpx + 0, chl);
            combine_slot(s1, nsh, nsl, wpx + 4, chl);
        }

        do_kstep(stg, 1, warp_m, warp_n, aoffl, boffl, c);

        CPWAIT0();
        __syncthreads();
    }

    // Epilogue: fragments -> global
    const int mrow = lid >> 2;
    const int ncol = (lid & 3) * 2;
    #pragma unroll
    for (int i = 0; i < 2; i++) {
        #pragma unroll
        for (int j = 0; j < 4; j++) {
            int m0 = warp_m * 32 + i * 16 + mrow;
            int n  = px0 + warp_n * 32 + j * 8 + ncol;
            float* p0 = out + ((size_t)(b * COUT + m0)) * HWSZ + y * WW + n;
            *(float2*)p0 = make_float2(c[i][j][0], c[i][j][1]);
            *(float2*)(p0 + 8 * HWSZ) = make_float2(c[i][j][2], c[i][j][3]);
        }
    }
}

// ---------------------------------------------------------------------------
extern "C" void kernel_launch(void* const* d_in, const int* in_sizes, int n_in,
                              void* d_out, int out_size)
{
    const float* x     = (const float*)d_in[0];
    const float* w_off = (const float*)d_in[1];
    const float* b_off = (const float*)d_in[2];
    const float* w_mod = (const float*)d_in[3];
    const float* b_mod = (const float*)d_in[4];
    const float* w_reg = (const float*)d_in[5];
    float* out = (float*)d_out;
    (void)in_sizes; (void)n_in; (void)out_size;

    const int smA = (XT + CIN * 9 * 28) * 4;
    cudaFuncSetAttribute(offmod_kernel, cudaFuncAttributeMaxDynamicSharedMemorySize, smA);
    cudaFuncSetAttribute(dcn_kernel,    cudaFuncAttributeMaxDynamicSharedMemorySize, SMEMB_TOTAL);

    wprep_kernel<<<(COUT * KTOT + 255) / 256, 256>>>(w_reg);

    dim3 gT(HWSZ / 64, NB);
    xt_kernel<<<gT, 256>>>(x);

    dim3 gA(WW / ATW, HH / ATH, NB);
    offmod_kernel<<<gA, 256, smA>>>(x, w_off, b_off, w_mod, b_mod);

    dim3 gB(2, HH, NB);
    dcn_kernel<<<gB, TBC, SMEMB_TOTAL>>>(out);
}

// round 13
// speedup vs baseline: 2.4492x; 1.1511x over previous
#include <cuda_runtime.h>
#include <cuda_bf16.h>
#include <cstdint>

#define HH 128
#define WW 128
#define HWSZ (HH*WW)
#define CIN 64
#define COUT 128
#define NB 4
#define KTOT 576      // CIN * 9
#define NCHUNK 18     // K chunks of 32

// ---------------- device scratch ----------------
__device__ float g_xt[NB * HWSZ * CIN];                 // x transposed: [b][hw][c]
__device__ __nv_bfloat16 g_wh[NCHUNK * 128 * 32];       // main W hi  [chunk][oc][kl]
__device__ __nv_bfloat16 g_wl[NCHUNK * 128 * 32];       // main W lo
__device__ __nv_bfloat16 g_womh[NCHUNK * 32 * 32];      // offset/mod W hi [chunk][32oc][kl]
__device__ __nv_bfloat16 g_woml[NCHUNK * 32 * 32];      // offset/mod W lo

__device__ __forceinline__ uint32_t smem_u32(const void* p) {
    uint32_t a;
    asm("{ .reg .u64 t; cvta.to.shared.u64 t, %1; cvt.u32.u64 %0, t; }" : "=r"(a) : "l"(p));
    return a;
}
__device__ __forceinline__ void ldm4(uint32_t* r, uint32_t addr) {
    asm volatile("ldmatrix.sync.aligned.m8n8.x4.shared.b16 {%0,%1,%2,%3}, [%4];"
                 : "=r"(r[0]), "=r"(r[1]), "=r"(r[2]), "=r"(r[3]) : "r"(addr));
}
__device__ __forceinline__ void mma_bf16(float* c, const uint32_t* a, const uint32_t* b) {
    asm volatile("mma.sync.aligned.m16n8k16.row.col.f32.bf16.bf16.f32 "
                 "{%0,%1,%2,%3}, {%4,%5,%6,%7}, {%8,%9}, {%0,%1,%2,%3};"
                 : "+f"(c[0]), "+f"(c[1]), "+f"(c[2]), "+f"(c[3])
                 : "r"(a[0]), "r"(a[1]), "r"(a[2]), "r"(a[3]), "r"(b[0]), "r"(b[1]));
}
__device__ __forceinline__ void cp16(uint32_t dst, const void* src) {
    asm volatile("cp.async.cg.shared.global [%0], [%1], 16;" :: "r"(dst), "l"(src));
}
#define CPCOMMIT() asm volatile("cp.async.commit_group;" ::: "memory")
#define CPWAIT0()  asm volatile("cp.async.wait_group 0;" ::: "memory")

// ---------------------------------------------------------------------------
// x transpose: [b][c][hw] -> [b][hw][c]
// ---------------------------------------------------------------------------
__global__ void xt_kernel(const float* __restrict__ x) {
    __shared__ float sm[64][65];
    const int tid = threadIdx.x;
    const int b   = blockIdx.y;
    const int hw0 = blockIdx.x * 64;
    const float* xb = x + (size_t)b * CIN * HWSZ;
    #pragma unroll
    for (int it = 0; it < 16; it++) {
        int c   = (tid >> 6) + it * 4;
        int hwl = tid & 63;
        sm[hwl][c] = xb[c * HWSZ + hw0 + hwl];
    }
    __syncthreads();
    float* xtb = g_xt + ((size_t)b * HWSZ + hw0) * CIN;
    #pragma unroll
    for (int it = 0; it < 16; it++) {
        int hwl = (tid >> 6) + it * 4;
        int cl  = tid & 63;
        xtb[hwl * CIN + cl] = sm[hwl][cl];
    }
}

// ---------------------------------------------------------------------------
// W prep (main conv): split into bf16 hi/lo, K reordered as k_new = tap*64 + c
// ---------------------------------------------------------------------------
__global__ void wprep_kernel(const float* __restrict__ w_reg) {
    int i = blockIdx.x * 256 + threadIdx.x;
    if (i >= COUT * KTOT) return;
    int oc = i / KTOT;
    int kn = i - oc * KTOT;
    int tap = kn >> 6;
    int c   = kn & 63;
    float v = w_reg[oc * KTOT + c * 9 + tap];
    __nv_bfloat16 h = __float2bfloat16_rn(v);
    float lo = v - __bfloat162float(h);
    int chunk = kn >> 5;
    int kl    = kn & 31;
    g_wh[(chunk * 128 + oc) * 32 + kl] = h;
    g_wl[(chunk * 128 + oc) * 32 + kl] = __float2bfloat16_rn(lo);
}

// ---------------------------------------------------------------------------
// W prep (offset+modulator conv): rows 0-17 = w_off, 18-26 = w_mod, 27-31 = 0
// ---------------------------------------------------------------------------
__global__ void wprep_om_kernel(const float* __restrict__ w_off,
                                const float* __restrict__ w_mod) {
    int i = blockIdx.x * 256 + threadIdx.x;
    if (i >= NCHUNK * 32 * 32) return;
    int chunk = i >> 10;
    int oc    = (i >> 5) & 31;
    int kl    = i & 31;
    int kn  = chunk * 32 + kl;
    int tap = kn >> 6;
    int c   = kn & 63;
    float v = 0.f;
    if (oc < 18)      v = w_off[(oc * CIN + c) * 9 + tap];
    else if (oc < 27) v = w_mod[((oc - 18) * CIN + c) * 9 + tap];
    __nv_bfloat16 h = __float2bfloat16_rn(v);
    float lo = v - __bfloat162float(h);
    g_womh[(chunk * 32 + oc) * 32 + kl] = h;
    g_woml[(chunk * 32 + oc) * 32 + kl] = __float2bfloat16_rn(lo);
}

// ---------------------------------------------------------------------------
// Fused kernel: loop1 = offset/mod GEMM (M=32), tables, loop2 = main GEMM.
// Block = 128 oc x 64 px, 256 threads / 8 warps, 2 CTAs per SM.
// ---------------------------------------------------------------------------
#define TBC 256
#define NPX 64
#define ROWB 80
#define WMATB (128 * ROWB)      // 10240
#define SMATB (NPX * ROWB)      // 5120
#define STAGEB (2 * WMATB + 2 * SMATB)   // 30720
#define SOFF   (2 * WMATB)
// loop1 sub-layout within a stage: Wom hi | Wom lo | S1 hi | S1 lo
#define W1MATB (32 * ROWB)      // 2560
#define S1OFF  (2 * W1MATB)     // 5120
#define CWB (2 * STAGEB)        // 61440
#define NTAB (9 * NPX)          // 576
#define CIB (CWB + 4 * NTAB * 4)           // 70656
#define OMB (CIB + 4 * NTAB * 4)           // 79872
#define OMSTRIDE 68
#define SMEMB_TOTAL (OMB + 32 * OMSTRIDE * 4)   // 88576

struct Slot {
    float4 a[4];
    float  w[4];
};

__device__ __forceinline__ void gather_slot(Slot& s, int tap, int px, const float* __restrict__ xq,
                                            int chl, const float* scw, const int* sci) {
    int idx = tap * NPX + px;
    s.w[0] = scw[idx]; s.w[1] = scw[idx+NTAB]; s.w[2] = scw[idx+2*NTAB]; s.w[3] = scw[idx+3*NTAB];
    int i0 = sci[idx], i1 = sci[idx+NTAB], i2 = sci[idx+2*NTAB], i3 = sci[idx+3*NTAB];
    s.a[0] = *(const float4*)(xq + (size_t)i0 * CIN + chl * 4);
    s.a[1] = *(const float4*)(xq + (size_t)i1 * CIN + chl * 4);
    s.a[2] = *(const float4*)(xq + (size_t)i2 * CIN + chl * 4);
    s.a[3] = *(const float4*)(xq + (size_t)i3 * CIN + chl * 4);
}

__device__ __forceinline__ void split_store(float v0, float v1, float v2, float v3,
                                            char* sh, char* sl, int px, int chl) {
    __nv_bfloat16 h0 = __float2bfloat16_rn(v0);
    __nv_bfloat16 h1 = __float2bfloat16_rn(v1);
    __nv_bfloat16 h2 = __float2bfloat16_rn(v2);
    __nv_bfloat16 h3 = __float2bfloat16_rn(v3);
    __nv_bfloat16 l0 = __float2bfloat16_rn(v0 - __bfloat162float(h0));
    __nv_bfloat16 l1 = __float2bfloat16_rn(v1 - __bfloat162float(h1));
    __nv_bfloat16 l2 = __float2bfloat16_rn(v2 - __bfloat162float(h2));
    __nv_bfloat16 l3 = __float2bfloat16_rn(v3 - __bfloat162float(h3));
    uint32_t hp0 = (uint32_t)__bfloat16_as_ushort(h0) | ((uint32_t)__bfloat16_as_ushort(h1) << 16);
    uint32_t hp1 = (uint32_t)__bfloat16_as_ushort(h2) | ((uint32_t)__bfloat16_as_ushort(h3) << 16);
    uint32_t lp0 = (uint32_t)__bfloat16_as_ushort(l0) | ((uint32_t)__bfloat16_as_ushort(l1) << 16);
    uint32_t lp1 = (uint32_t)__bfloat16_as_ushort(l2) | ((uint32_t)__bfloat16_as_ushort(l3) << 16);
    *(uint2*)(sh + px * ROWB + chl * 8) = make_uint2(hp0, hp1);
    *(uint2*)(sl + px * ROWB + chl * 8) = make_uint2(lp0, lp1);
}

__device__ __forceinline__ void combine_slot(const Slot& s, char* sh, char* sl, int px, int chl) {
    float v0 = s.w[0]*s.a[0].x + s.w[1]*s.a[1].x + s.w[2]*s.a[2].x + s.w[3]*s.a[3].x;
    float v1 = s.w[0]*s.a[0].y + s.w[1]*s.a[1].y + s.w[2]*s.a[2].y + s.w[3]*s.a[3].y;
    float v2 = s.w[0]*s.a[0].z + s.w[1]*s.a[1].z + s.w[2]*s.a[2].z + s.w[3]*s.a[3].z;
    float v3 = s.w[0]*s.a[0].w + s.w[1]*s.a[1].w + s.w[2]*s.a[2].w + s.w[3]*s.a[3].w;
    split_store(v0, v1, v2, v3, sh, sl, px, chl);
}

__device__ __forceinline__ void wcopy_async(int chunk, uint32_t stg, int tid) {
    const char* srcH = (const char*)g_wh + (size_t)chunk * 128 * 64;
    const char* srcL = (const char*)g_wl + (size_t)chunk * 128 * 64;
    #pragma unroll
    for (int it = 0; it < 4; it++) {
        int i = tid + it * TBC;
        int mat = i >> 9;
        int rr  = (i >> 2) & 127;
        int c4  = i & 3;
        const char* src = (mat ? srcL : srcH) + rr * 64 + c4 * 16;
        cp16(stg + (uint32_t)(mat * WMATB + rr * ROWB + c4 * 16), src);
    }
}

__device__ __forceinline__ void w1copy_async(int chunk, uint32_t stg, int tid) {
    // 2 mats x 32 rows x 4 float4 = 256 cp16 -> 1 per thread
    int mat = tid >> 7;
    int rr  = (tid >> 2) & 31;
    int c4  = tid & 3;
    const char* src = (mat ? (const char*)g_woml : (const char*)g_womh)
                      + (size_t)chunk * 2048 + rr * 64 + c4 * 16;
    cp16(stg + (uint32_t)(mat * W1MATB + rr * ROWB + c4 * 16), src);
}

__device__ __forceinline__ void do_kstep(uint32_t stg, int ks, int warp_m, int warp_n,
                                         uint32_t aoffl, uint32_t boffl, float c[2][4][4]) {
    const uint32_t abase = stg + (uint32_t)(warp_m * 32 * ROWB + ks * 32) + aoffl;
    uint32_t ah[2][4], al[2][4];
    ldm4(ah[0], abase);
    ldm4(ah[1], abase + 16 * ROWB);
    ldm4(al[0], abase + WMATB);
    ldm4(al[1], abase + WMATB + 16 * ROWB);
    const uint32_t bbase = stg + (uint32_t)(SOFF + warp_n * 32 * ROWB + ks * 32) + boffl;
    uint32_t bh[4][2], bl[4][2];
    #pragma unroll
    for (int jj = 0; jj < 2; jj++) {
        uint32_t tmp[4];
        ldm4(tmp, bbase + (uint32_t)(jj * 16 * ROWB));
        bh[2*jj][0] = tmp[0]; bh[2*jj][1] = tmp[1];
        bh[2*jj+1][0] = tmp[2]; bh[2*jj+1][1] = tmp[3];
        ldm4(tmp, bbase + (uint32_t)(SMATB + jj * 16 * ROWB));
        bl[2*jj][0] = tmp[0]; bl[2*jj][1] = tmp[1];
        bl[2*jj+1][0] = tmp[2]; bl[2*jj+1][1] = tmp[3];
    }
    #pragma unroll
    for (int i = 0; i < 2; i++) {
        #pragma unroll
        for (int j = 0; j < 4; j++) {
            mma_bf16(c[i][j], ah[i], bh[j]);
            mma_bf16(c[i][j], ah[i], bl[j]);
            mma_bf16(c[i][j], al[i], bh[j]);
        }
    }
}

__device__ __forceinline__ void do_kstep1(uint32_t stg, int ks, uint32_t aoffl,
                                          const uint32_t bh4[4], const uint32_t bl4[4],
                                          float c1[2][4]) {
    const uint32_t abase = stg + (uint32_t)(ks * 32) + aoffl;
    uint32_t ah[2][4], al[2][4];
    ldm4(ah[0], abase);
    ldm4(ah[1], abase + 16 * ROWB);
    ldm4(al[0], abase + W1MATB);
    ldm4(al[1], abase + W1MATB + 16 * ROWB);
    uint32_t bh[2] = { bh4[2*ks], bh4[2*ks+1] };
    uint32_t bl[2] = { bl4[2*ks], bl4[2*ks+1] };
    #pragma unroll
    for (int i = 0; i < 2; i++) {
        mma_bf16(c1[i], ah[i], bh);
        mma_bf16(c1[i], ah[i], bl);
        mma_bf16(c1[i], al[i], bh);
    }
}

__global__ void __launch_bounds__(TBC, 2) dcn_kernel(const float* __restrict__ b_off,
                                                     const float* __restrict__ b_mod,
                                                     float* __restrict__ out)
{
    extern __shared__ char smb[];
    const uint32_t sb = smem_u32(smb);
    float* scw = (float*)(smb + CWB);
    int*   sci = (int*)(smb + CIB);
    float* som = (float*)(smb + OMB);

    const int tid  = threadIdx.x;
    const int wid  = tid >> 5;
    const int lid  = tid & 31;
    const int half = blockIdx.x;
    const int y    = blockIdx.y;
    const int b    = blockIdx.z;
    const int px0  = half * NPX;
    const float* __restrict__ xtb = g_xt + (size_t)b * HWSZ * CIN;

    // Lane maps (shared by both loops)
    const int warp_m = wid & 3;
    const int warp_n = wid >> 2;
    const uint32_t aoffl = (uint32_t)((lid & 15) * ROWB + (lid >> 4) * 16);
    const uint32_t boffl = (uint32_t)(((lid & 7) + ((lid >> 4) ? 8 : 0)) * ROWB + ((lid >> 3) & 1) * 16);
    const int chl = lid & 7;
    const int wpx = wid * 8 + (lid >> 3);
    const uint32_t b1offl = (uint32_t)((wid * 8 + (lid & 7)) * ROWB + (lid >> 3) * 16);

    // plain (non-deformed) im2col load for loop1
    auto plain_load = [&](int px_l, int tap, int cg) -> float4 {
        int gy = y + tap / 3 - 1;
        int gx = px0 + px_l + tap % 3 - 1;
        if (gy >= 0 && gy < HH && gx >= 0 && gx < WW)
            return *(const float4*)(xtb + (size_t)(gy * WW + gx) * CIN + cg * 32 + chl * 4);
        return make_float4(0.f, 0.f, 0.f, 0.f);
    };

    // ---------------- Loop 1: offset/modulator GEMM (M=32, N=64, K=576) ----
    float c1[2][4];
    #pragma unroll
    for (int i = 0; i < 2; i++)
        #pragma unroll
        for (int q = 0; q < 4; q++) c1[i][q] = 0.f;

    {   // prologue chunk 0
        w1copy_async(0, sb, tid);
        CPCOMMIT();
        char* sh = smb + S1OFF;
        char* sl = smb + S1OFF + SMATB;
        #pragma unroll
        for (int j = 0; j < 2; j++) {
            float4 v = plain_load(wpx + j * 4, 0, 0);
            split_store(v.x, v.y, v.z, v.w, sh, sl, wpx + j * 4, chl);
        }
        CPWAIT0();
        __syncthreads();
    }

    for (int t = 0; t < NCHUNK; t++) {
        const int s = t & 1;
        const int ns = s ^ 1;
        const uint32_t stg = sb + (uint32_t)(s * STAGEB);
        char* nsh = smb + ns * STAGEB + S1OFF;
        char* nsl = smb + ns * STAGEB + S1OFF + SMATB;

        float4 v0, v1;
        if (t < NCHUNK - 1) {
            const int u = t + 1;
            w1copy_async(u, sb + (uint32_t)(ns * STAGEB), tid);
            CPCOMMIT();
            v0 = plain_load(wpx + 0, u >> 1, u & 1);
            v1 = plain_load(wpx + 4, u >> 1, u & 1);
        }

        uint32_t bh4[4], bl4[4];
        ldm4(bh4, stg + (uint32_t)S1OFF + b1offl);
        ldm4(bl4, stg + (uint32_t)(S1OFF + SMATB) + b1offl);

        do_kstep1(stg, 0, aoffl, bh4, bl4, c1);

        if (t < NCHUNK - 1) {
            split_store(v0.x, v0.y, v0.z, v0.w, nsh, nsl, wpx + 0, chl);
            split_store(v1.x, v1.y, v1.z, v1.w, nsh, nsl, wpx + 4, chl);
        }

        do_kstep1(stg, 1, aoffl, bh4, bl4, c1);

        CPWAIT0();
        __syncthreads();
    }

    // write om fragments -> smem with bias + sigmoid
    {
        const int r0 = (lid >> 2);
        const int c0 = wid * 8 + (lid & 3) * 2;
        #pragma unroll
        for (int i = 0; i < 2; i++) {
            #pragma unroll
            for (int h2 = 0; h2 < 2; h2++) {
                int row = i * 16 + h2 * 8 + r0;
                float va = c1[i][h2 * 2 + 0];
                float vb = c1[i][h2 * 2 + 1];
                float bias = (row < 18) ? b_off[row] : (row < 27 ? b_mod[row - 18] : 0.f);
                va += bias; vb += bias;
                if (row >= 18 && row < 27) {
                    va = 2.f / (1.f + __expf(-va));
                    vb = 2.f / (1.f + __expf(-vb));
                }
                som[row * OMSTRIDE + c0]     = va;
                som[row * OMSTRIDE + c0 + 1] = vb;
            }
        }
    }
    __syncthreads();

    // ---------------- tables: bilinear coords from smem om ----------------
    for (int i = tid; i < NTAB; i += TBC) {
        int k = i / NPX;
        int p = i - k * NPX;
        int gx = px0 + p;
        float dy = som[(2*k)   * OMSTRIDE + p];
        float dx = som[(2*k+1) * OMSTRIDE + p];
        float m  = som[(18+k)  * OMSTRIDE + p];
        float pyf = (float)(y  + k / 3 - 1) + dy;
        float pxf = (float)(gx + k % 3 - 1) + dx;
        float fy = floorf(pyf);
        float fx = floorf(pxf);
        float ty = pyf - fy;
        float tx = pxf - fx;
        int iy0 = (int)fy, ix0 = (int)fx;
        int iy1 = iy0 + 1, ix1 = ix0 + 1;
        float vy0 = (iy0 >= 0 && iy0 <= HH-1) ? 1.f : 0.f;
        float vy1 = (iy1 >= 0 && iy1 <= HH-1) ? 1.f : 0.f;
        float vx0 = (ix0 >= 0 && ix0 <= WW-1) ? 1.f : 0.f;
        float vx1 = (ix1 >= 0 && ix1 <= WW-1) ? 1.f : 0.f;
        int cy0 = min(max(iy0, 0), HH-1);
        int cy1 = min(max(iy1, 0), HH-1);
        int cx0 = min(max(ix0, 0), WW-1);
        int cx1 = min(max(ix1, 0), WW-1);
        scw[i         ] = (1.f - ty) * (1.f - tx) * m * vy0 * vx0;
        scw[NTAB   + i] = (1.f - ty) * tx         * m * vy0 * vx1;
        scw[2*NTAB + i] = ty * (1.f - tx)         * m * vy1 * vx0;
        scw[3*NTAB + i] = ty * tx                 * m * vy1 * vx1;
        sci[i         ] = cy0 * WW + cx0;
        sci[NTAB   + i] = cy0 * WW + cx1;
        sci[2*NTAB + i] = cy1 * WW + cx0;
        sci[3*NTAB + i] = cy1 * WW + cx1;
    }
    __syncthreads();

    // ---------------- Loop 2: main deformable GEMM (M=128, N=64, K=576) ----
    float c[2][4][4];
    #pragma unroll
    for (int i = 0; i < 2; i++)
        #pragma unroll
        for (int j = 0; j < 4; j++)
            #pragma unroll
            for (int q = 0; q < 4; q++) c[i][j][q] = 0.f;

    {   // prologue chunk 0
        wcopy_async(0, sb, tid);
        CPCOMMIT();
        char* sh = smb + SOFF;
        char* sl = smb + SOFF + SMATB;
        Slot s;
        #pragma unroll
        for (int j = 0; j < 2; j++) {
            gather_slot(s, 0, wpx + j * 4, xtb, chl, scw, sci);
            combine_slot(s, sh, sl, wpx + j * 4, chl);
        }
        CPWAIT0();
        __syncthreads();
    }

    for (int t = 0; t < NCHUNK; t++) {
        const int s = t & 1;
        const int ns = s ^ 1;
        const uint32_t stg = sb + (uint32_t)(s * STAGEB);
        char* nsh = smb + ns * STAGEB + SOFF;
        char* nsl = smb + ns * STAGEB + SOFF + SMATB;

        Slot s0, s1;
        const int u = t + 1;
        const int tap = u >> 1;
        const float* __restrict__ xq = xtb + ((u & 1) << 5);

        if (t < NCHUNK - 1) {
            wcopy_async(u, sb + (uint32_t)(ns * STAGEB), tid);
            CPCOMMIT();
            gather_slot(s0, tap, wpx + 0, xq, chl, scw, sci);
            gather_slot(s1, tap, wpx + 4, xq, chl, scw, sci);
        }

        do_kstep(stg, 0, warp_m, warp_n, aoffl, boffl, c);

        if (t < NCHUNK - 1) {
            combine_slot(s0, nsh, nsl, wpx + 0, chl);
            combine_slot(s1, nsh, nsl, wpx + 4, chl);
        }

        do_kstep(stg, 1, warp_m, warp_n, aoffl, boffl, c);

        CPWAIT0();
        __syncthreads();
    }

    // Epilogue: fragments -> global
    const int mrow = lid >> 2;
    const int ncol = (lid & 3) * 2;
    #pragma unroll
    for (int i = 0; i < 2; i++) {
        #pragma unroll
        for (int j = 0; j < 4; j++) {
            int m0 = warp_m * 32 + i * 16 + mrow;
            int n  = px0 + warp_n * 32 + j * 8 + ncol;
            float* p0 = out + ((size_t)(b * COUT + m0)) * HWSZ + y * WW + n;
            *(float2*)p0 = make_float2(c[i][j][0], c[i][j][1]);
            *(float2*)(p0 + 8 * HWSZ) = make_float2(c[i][j][2], c[i][j][3]);
        }
    }
}

// ---------------------------------------------------------------------------
extern "C" void kernel_launch(void* const* d_in, const int* in_sizes, int n_in,
                              void* d_out, int out_size)
{
    const float* x     = (const float*)d_in[0];
    const float* w_off = (const float*)d_in[1];
    const float* b_off = (const float*)d_in[2];
    const float* w_mod = (const float*)d_in[3];
    const float* b_mod = (const float*)d_in[4];
    const float* w_reg = (const float*)d_in[5];
    float* out = (float*)d_out;
    (void)in_sizes; (void)n_in; (void)out_size;

    cudaFuncSetAttribute(dcn_kernel, cudaFuncAttributeMaxDynamicSharedMemorySize, SMEMB_TOTAL);

    wprep_kernel<<<(COUT * KTOT + 255) / 256, 256>>>(w_reg);
    wprep_om_kernel<<<(NCHUNK * 32 * 32 + 255) / 256, 256>>>(w_off, w_mod);

    dim3 gT(HWSZ / 64, NB);
    xt_kernel<<<gT, 256>>>(x);

    dim3 gB(2, HH, NB);
    dcn_kernel<<<gB, TBC, SMEMB_TOTAL>>>(b_off, b_mod, out);
}

// round 14
// speedup vs baseline: 2.6122x; 1.0666x over previous
#include <cuda_runtime.h>
#include <cuda_bf16.h>
#include <cstdint>

#define HH 128
#define WW 128
#define HWSZ (HH*WW)
#define CIN 64
#define COUT 128
#define NB 4
#define KTOT 576      // CIN * 9
#define NCHUNK 18     // K chunks of 32

// ---------------- device scratch ----------------
__device__ float g_xt[NB * HWSZ * CIN];                 // x transposed: [b][hw][c]
__device__ __nv_bfloat16 g_wh[NCHUNK * 128 * 32];       // main W hi  [chunk][oc][kl]
__device__ __nv_bfloat16 g_wl[NCHUNK * 128 * 32];       // main W lo
__device__ __nv_bfloat16 g_womh[NCHUNK * 32 * 32];      // offset/mod W hi [chunk][32oc][kl]
__device__ __nv_bfloat16 g_woml[NCHUNK * 32 * 32];      // offset/mod W lo

__device__ __forceinline__ uint32_t smem_u32(const void* p) {
    uint32_t a;
    asm("{ .reg .u64 t; cvta.to.shared.u64 t, %1; cvt.u32.u64 %0, t; }" : "=r"(a) : "l"(p));
    return a;
}
__device__ __forceinline__ void ldm4(uint32_t* r, uint32_t addr) {
    asm volatile("ldmatrix.sync.aligned.m8n8.x4.shared.b16 {%0,%1,%2,%3}, [%4];"
                 : "=r"(r[0]), "=r"(r[1]), "=r"(r[2]), "=r"(r[3]) : "r"(addr));
}
__device__ __forceinline__ void mma_bf16(float* c, const uint32_t* a, const uint32_t* b) {
    asm volatile("mma.sync.aligned.m16n8k16.row.col.f32.bf16.bf16.f32 "
                 "{%0,%1,%2,%3}, {%4,%5,%6,%7}, {%8,%9}, {%0,%1,%2,%3};"
                 : "+f"(c[0]), "+f"(c[1]), "+f"(c[2]), "+f"(c[3])
                 : "r"(a[0]), "r"(a[1]), "r"(a[2]), "r"(a[3]), "r"(b[0]), "r"(b[1]));
}
__device__ __forceinline__ void cp16(uint32_t dst, const void* src) {
    asm volatile("cp.async.cg.shared.global [%0], [%1], 16;" :: "r"(dst), "l"(src));
}
#define CPCOMMIT() asm volatile("cp.async.commit_group;" ::: "memory")
#define CPWAIT0()  asm volatile("cp.async.wait_group 0;" ::: "memory")

// ---------------- packed f32x2 helpers (Blackwell sm_100 ISA) ----------------
__device__ __forceinline__ uint64_t packw2(float w) {
    uint64_t d; asm("mov.b64 %0, {%1, %1};" : "=l"(d) : "f"(w)); return d;
}
__device__ __forceinline__ uint64_t mul2(uint64_t a, uint64_t b) {
    uint64_t d; asm("mul.rn.f32x2 %0, %1, %2;" : "=l"(d) : "l"(a), "l"(b)); return d;
}
__device__ __forceinline__ uint64_t fma2(uint64_t a, uint64_t b, uint64_t c) {
    uint64_t d; asm("fma.rn.f32x2 %0, %1, %2, %3;" : "=l"(d) : "l"(a), "l"(b), "l"(c)); return d;
}
__device__ __forceinline__ uint32_t cvt_bf16x2(uint64_t v) {
    uint32_t r;
    asm("{ .reg .b32 lo, hi; mov.b64 {lo, hi}, %1; cvt.rn.bf16x2.f32 %0, hi, lo; }"
        : "=r"(r) : "l"(v));
    return r;
}
__device__ __forceinline__ uint64_t bf16x2_to_f32x2(uint32_t h) {
    uint64_t d;
    asm("{ .reg .b32 f0, f1; prmt.b32 f0, %1, 0, 0x1044; prmt.b32 f1, %1, 0, 0x3244; mov.b64 %0, {f0, f1}; }"
        : "=l"(d) : "r"(h));
    return d;
}
#define NEG1X2 0xBF800000BF800000ULL

// ---------------------------------------------------------------------------
// x transpose: [b][c][hw] -> [b][hw][c]
// ---------------------------------------------------------------------------
__global__ void xt_kernel(const float* __restrict__ x) {
    __shared__ float sm[64][65];
    const int tid = threadIdx.x;
    const int b   = blockIdx.y;
    const int hw0 = blockIdx.x * 64;
    const float* xb = x + (size_t)b * CIN * HWSZ;
    #pragma unroll
    for (int it = 0; it < 16; it++) {
        int c   = (tid >> 6) + it * 4;
        int hwl = tid & 63;
        sm[hwl][c] = xb[c * HWSZ + hw0 + hwl];
    }
    __syncthreads();
    float* xtb = g_xt + ((size_t)b * HWSZ + hw0) * CIN;
    #pragma unroll
    for (int it = 0; it < 16; it++) {
        int hwl = (tid >> 6) + it * 4;
        int cl  = tid & 63;
        xtb[hwl * CIN + cl] = sm[hwl][cl];
    }
}

// ---------------------------------------------------------------------------
// W prep (main conv)
// ---------------------------------------------------------------------------
__global__ void wprep_kernel(const float* __restrict__ w_reg) {
    int i = blockIdx.x * 256 + threadIdx.x;
    if (i >= COUT * KTOT) return;
    int oc = i / KTOT;
    int kn = i - oc * KTOT;
    int tap = kn >> 6;
    int c   = kn & 63;
    float v = w_reg[oc * KTOT + c * 9 + tap];
    __nv_bfloat16 h = __float2bfloat16_rn(v);
    float lo = v - __bfloat162float(h);
    int chunk = kn >> 5;
    int kl    = kn & 31;
    g_wh[(chunk * 128 + oc) * 32 + kl] = h;
    g_wl[(chunk * 128 + oc) * 32 + kl] = __float2bfloat16_rn(lo);
}

// ---------------------------------------------------------------------------
// W prep (offset+modulator conv)
// ---------------------------------------------------------------------------
__global__ void wprep_om_kernel(const float* __restrict__ w_off,
                                const float* __restrict__ w_mod) {
    int i = blockIdx.x * 256 + threadIdx.x;
    if (i >= NCHUNK * 32 * 32) return;
    int chunk = i >> 10;
    int oc    = (i >> 5) & 31;
    int kl    = i & 31;
    int kn  = chunk * 32 + kl;
    int tap = kn >> 6;
    int c   = kn & 63;
    float v = 0.f;
    if (oc < 18)      v = w_off[(oc * CIN + c) * 9 + tap];
    else if (oc < 27) v = w_mod[((oc - 18) * CIN + c) * 9 + tap];
    __nv_bfloat16 h = __float2bfloat16_rn(v);
    float lo = v - __bfloat162float(h);
    g_womh[(chunk * 32 + oc) * 32 + kl] = h;
    g_woml[(chunk * 32 + oc) * 32 + kl] = __float2bfloat16_rn(lo);
}

// ---------------------------------------------------------------------------
// Fused kernel layout
// ---------------------------------------------------------------------------
#define TBC 256
#define NPX 64
#define ROWB 80
#define WMATB (128 * ROWB)      // 10240
#define SMATB (NPX * ROWB)      // 5120
#define STAGEB (2 * WMATB + 2 * SMATB)   // 30720
#define SOFF   (2 * WMATB)
#define W1MATB (32 * ROWB)      // 2560
#define S1OFF  (2 * W1MATB)     // 5120
#define CWB (2 * STAGEB)        // 61440: float2 (w, idx-bits) tables, 4 planes
#define NTAB (9 * NPX)          // 576
#define OMB (CWB + 4 * NTAB * 8)           // 79872
#define OMSTRIDE 68
#define SMEMB_TOTAL (OMB + 32 * OMSTRIDE * 4)   // 88576

struct Slot2 {
    ulonglong2 a[4];
    float w[4];
};

__device__ __forceinline__ void gather_slot(Slot2& s, int tap, int px, const float* __restrict__ xq,
                                            int chl, const float2* sct) {
    int idx = tap * NPX + px;
    #pragma unroll
    for (int c = 0; c < 4; c++) {
        float2 t = sct[c * NTAB + idx];
        s.w[c] = t.x;
        int lin = __float_as_int(t.y);
        s.a[c] = *(const ulonglong2*)(xq + (size_t)lin * CIN + chl * 4);
    }
}

__device__ __forceinline__ void split_store2(uint64_t v01, uint64_t v23,
                                             char* sh, char* sl, int px, int chl) {
    uint32_t h01 = cvt_bf16x2(v01);
    uint32_t h23 = cvt_bf16x2(v23);
    uint64_t l01 = fma2(bf16x2_to_f32x2(h01), NEG1X2, v01);
    uint64_t l23 = fma2(bf16x2_to_f32x2(h23), NEG1X2, v23);
    *(uint2*)(sh + px * ROWB + chl * 8) = make_uint2(h01, h23);
    *(uint2*)(sl + px * ROWB + chl * 8) = make_uint2(cvt_bf16x2(l01), cvt_bf16x2(l23));
}

__device__ __forceinline__ void combine_slot(const Slot2& s, char* sh, char* sl, int px, int chl) {
    uint64_t w0 = packw2(s.w[0]);
    uint64_t w1 = packw2(s.w[1]);
    uint64_t w2 = packw2(s.w[2]);
    uint64_t w3 = packw2(s.w[3]);
    uint64_t v01 = mul2(w0, s.a[0].x);
    v01 = fma2(w1, s.a[1].x, v01);
    v01 = fma2(w2, s.a[2].x, v01);
    v01 = fma2(w3, s.a[3].x, v01);
    uint64_t v23 = mul2(w0, s.a[0].y);
    v23 = fma2(w1, s.a[1].y, v23);
    v23 = fma2(w2, s.a[2].y, v23);
    v23 = fma2(w3, s.a[3].y, v23);
    split_store2(v01, v23, sh, sl, px, chl);
}

__device__ __forceinline__ void wcopy_async(int chunk, uint32_t stg, int tid) {
    const char* srcH = (const char*)g_wh + (size_t)chunk * 128 * 64;
    const char* srcL = (const char*)g_wl + (size_t)chunk * 128 * 64;
    #pragma unroll
    for (int it = 0; it < 4; it++) {
        int i = tid + it * TBC;
        int mat = i >> 9;
        int rr  = (i >> 2) & 127;
        int c4  = i & 3;
        const char* src = (mat ? srcL : srcH) + rr * 64 + c4 * 16;
        cp16(stg + (uint32_t)(mat * WMATB + rr * ROWB + c4 * 16), src);
    }
}

__device__ __forceinline__ void w1copy_async(int chunk, uint32_t stg, int tid) {
    int mat = tid >> 7;
    int rr  = (tid >> 2) & 31;
    int c4  = tid & 3;
    const char* src = (mat ? (const char*)g_woml : (const char*)g_womh)
                      + (size_t)chunk * 2048 + rr * 64 + c4 * 16;
    cp16(stg + (uint32_t)(mat * W1MATB + rr * ROWB + c4 * 16), src);
}

__device__ __forceinline__ void do_kstep(uint32_t stg, int ks, int warp_m, int warp_n,
                                         uint32_t aoffl, uint32_t boffl, float c[2][4][4]) {
    const uint32_t abase = stg + (uint32_t)(warp_m * 32 * ROWB + ks * 32) + aoffl;
    uint32_t ah[2][4], al[2][4];
    ldm4(ah[0], abase);
    ldm4(ah[1], abase + 16 * ROWB);
    ldm4(al[0], abase + WMATB);
    ldm4(al[1], abase + WMATB + 16 * ROWB);
    const uint32_t bbase = stg + (uint32_t)(SOFF + warp_n * 32 * ROWB + ks * 32) + boffl;
    uint32_t bh[4][2], bl[4][2];
    #pragma unroll
    for (int jj = 0; jj < 2; jj++) {
        uint32_t tmp[4];
        ldm4(tmp, bbase + (uint32_t)(jj * 16 * ROWB));
        bh[2*jj][0] = tmp[0]; bh[2*jj][1] = tmp[1];
        bh[2*jj+1][0] = tmp[2]; bh[2*jj+1][1] = tmp[3];
        ldm4(tmp, bbase + (uint32_t)(SMATB + jj * 16 * ROWB));
        bl[2*jj][0] = tmp[0]; bl[2*jj][1] = tmp[1];
        bl[2*jj+1][0] = tmp[2]; bl[2*jj+1][1] = tmp[3];
    }
    #pragma unroll
    for (int i = 0; i < 2; i++) {
        #pragma unroll
        for (int j = 0; j < 4; j++) {
            mma_bf16(c[i][j], ah[i], bh[j]);
            mma_bf16(c[i][j], ah[i], bl[j]);
            mma_bf16(c[i][j], al[i], bh[j]);
        }
    }
}

__device__ __forceinline__ void do_kstep1(uint32_t stg, int ks, uint32_t aoffl,
                                          const uint32_t bh4[4], const uint32_t bl4[4],
                                          float c1[2][4]) {
    const uint32_t abase = stg + (uint32_t)(ks * 32) + aoffl;
    uint32_t ah[2][4], al[2][4];
    ldm4(ah[0], abase);
    ldm4(ah[1], abase + 16 * ROWB);
    ldm4(al[0], abase + W1MATB);
    ldm4(al[1], abase + W1MATB + 16 * ROWB);
    uint32_t bh[2] = { bh4[2*ks], bh4[2*ks+1] };
    uint32_t bl[2] = { bl4[2*ks], bl4[2*ks+1] };
    #pragma unroll
    for (int i = 0; i < 2; i++) {
        mma_bf16(c1[i], ah[i], bh);
        mma_bf16(c1[i], ah[i], bl);
        mma_bf16(c1[i], al[i], bh);
    }
}

__global__ void __launch_bounds__(TBC, 2) dcn_kernel(const float* __restrict__ b_off,
                                                     const float* __restrict__ b_mod,
                                                     float* __restrict__ out)
{
    extern __shared__ char smb[];
    const uint32_t sb = smem_u32(smb);
    float2* sct = (float2*)(smb + CWB);
    float*  som = (float*)(smb + OMB);

    const int tid  = threadIdx.x;
    const int wid  = tid >> 5;
    const int lid  = tid & 31;
    const int half = blockIdx.x;
    const int y    = blockIdx.y;
    const int b    = blockIdx.z;
    const int px0  = half * NPX;
    const float* __restrict__ xtb = g_xt + (size_t)b * HWSZ * CIN;

    // Lane maps (shared by both loops)
    const int warp_m = wid & 3;
    const int warp_n = wid >> 2;
    const uint32_t aoffl = (uint32_t)((lid & 15) * ROWB + (lid >> 4) * 16);
    const uint32_t boffl = (uint32_t)(((lid & 7) + ((lid >> 4) ? 8 : 0)) * ROWB + ((lid >> 3) & 1) * 16);
    const int chl = lid & 7;
    const int wpx = wid * 8 + (lid >> 3);
    const uint32_t b1offl = (uint32_t)((wid * 8 + (lid & 7)) * ROWB + (lid >> 3) * 16);

    // plain (non-deformed) im2col load for loop1
    auto plain_load = [&](int px_l, int tap, int cg) -> ulonglong2 {
        int gy = y + tap / 3 - 1;
        int gx = px0 + px_l + tap % 3 - 1;
        if (gy >= 0 && gy < HH && gx >= 0 && gx < WW)
            return *(const ulonglong2*)(xtb + (size_t)(gy * WW + gx) * CIN + cg * 32 + chl * 4);
        ulonglong2 z; z.x = 0ULL; z.y = 0ULL;
        return z;
    };

    // ---------------- Loop 1: offset/modulator GEMM (M=32, N=64, K=576) ----
    float c1[2][4];
    #pragma unroll
    for (int i = 0; i < 2; i++)
        #pragma unroll
        for (int q = 0; q < 4; q++) c1[i][q] = 0.f;

    {   // prologue chunk 0
        w1copy_async(0, sb, tid);
        CPCOMMIT();
        char* sh = smb + S1OFF;
        char* sl = smb + S1OFF + SMATB;
        #pragma unroll
        for (int j = 0; j < 2; j++) {
            ulonglong2 v = plain_load(wpx + j * 4, 0, 0);
            split_store2(v.x, v.y, sh, sl, wpx + j * 4, chl);
        }
        CPWAIT0();
        __syncthreads();
    }

    for (int t = 0; t < NCHUNK; t++) {
        const int s = t & 1;
        const int ns = s ^ 1;
        const uint32_t stg = sb + (uint32_t)(s * STAGEB);
        char* nsh = smb + ns * STAGEB + S1OFF;
        char* nsl = smb + ns * STAGEB + S1OFF + SMATB;

        ulonglong2 v0, v1;
        if (t < NCHUNK - 1) {
            const int u = t + 1;
            w1copy_async(u, sb + (uint32_t)(ns * STAGEB), tid);
            CPCOMMIT();
            v0 = plain_load(wpx + 0, u >> 1, u & 1);
            v1 = plain_load(wpx + 4, u >> 1, u & 1);
        }

        uint32_t bh4[4], bl4[4];
        ldm4(bh4, stg + (uint32_t)S1OFF + b1offl);
        ldm4(bl4, stg + (uint32_t)(S1OFF + SMATB) + b1offl);

        do_kstep1(stg, 0, aoffl, bh4, bl4, c1);

        if (t < NCHUNK - 1) {
            split_store2(v0.x, v0.y, nsh, nsl, wpx + 0, chl);
            split_store2(v1.x, v1.y, nsh, nsl, wpx + 4, chl);
        }

        do_kstep1(stg, 1, aoffl, bh4, bl4, c1);

        CPWAIT0();
        __syncthreads();
    }

    // write om fragments -> smem with bias + sigmoid
    {
        const int r0 = (lid >> 2);
        const int c0 = wid * 8 + (lid & 3) * 2;
        #pragma unroll
        for (int i = 0; i < 2; i++) {
            #pragma unroll
            for (int h2 = 0; h2 < 2; h2++) {
                int row = i * 16 + h2 * 8 + r0;
                float va = c1[i][h2 * 2 + 0];
                float vb = c1[i][h2 * 2 + 1];
                float bias = (row < 18) ? b_off[row] : (row < 27 ? b_mod[row - 18] : 0.f);
                va += bias; vb += bias;
                if (row >= 18 && row < 27) {
                    va = 2.f / (1.f + __expf(-va));
                    vb = 2.f / (1.f + __expf(-vb));
                }
                som[row * OMSTRIDE + c0]     = va;
                som[row * OMSTRIDE + c0 + 1] = vb;
            }
        }
    }
    __syncthreads();

    // ---------------- tables: bilinear coords from smem om ----------------
    for (int i = tid; i < NTAB; i += TBC) {
        int k = i / NPX;
        int p = i - k * NPX;
        int gx = px0 + p;
        float dy = som[(2*k)   * OMSTRIDE + p];
        float dx = som[(2*k+1) * OMSTRIDE + p];
        float m  = som[(18+k)  * OMSTRIDE + p];
        float pyf = (float)(y  + k / 3 - 1) + dy;
        float pxf = (float)(gx + k % 3 - 1) + dx;
        float fy = floorf(pyf);
        float fx = floorf(pxf);
        float ty = pyf - fy;
        float tx = pxf - fx;
        int iy0 = (int)fy, ix0 = (int)fx;
        int iy1 = iy0 + 1, ix1 = ix0 + 1;
        float vy0 = (iy0 >= 0 && iy0 <= HH-1) ? 1.f : 0.f;
        float vy1 = (iy1 >= 0 && iy1 <= HH-1) ? 1.f : 0.f;
        float vx0 = (ix0 >= 0 && ix0 <= WW-1) ? 1.f : 0.f;
        float vx1 = (ix1 >= 0 && ix1 <= WW-1) ? 1.f : 0.f;
        int cy0 = min(max(iy0, 0), HH-1);
        int cy1 = min(max(iy1, 0), HH-1);
        int cx0 = min(max(ix0, 0), WW-1);
        int cx1 = min(max(ix1, 0), WW-1);
        sct[i         ] = make_float2((1.f - ty) * (1.f - tx) * m * vy0 * vx0, __int_as_float(cy0 * WW + cx0));
        sct[NTAB   + i] = make_float2((1.f - ty) * tx         * m * vy0 * vx1, __int_as_float(cy0 * WW + cx1));
        sct[2*NTAB + i] = make_float2(ty * (1.f - tx)         * m * vy1 * vx0, __int_as_float(cy1 * WW + cx0));
        sct[3*NTAB + i] = make_float2(ty * tx                 * m * vy1 * vx1, __int_as_float(cy1 * WW + cx1));
    }
    __syncthreads();

    // ---------------- Loop 2: main deformable GEMM (M=128, N=64, K=576) ----
    float c[2][4][4];
    #pragma unroll
    for (int i = 0; i < 2; i++)
        #pragma unroll
        for (int j = 0; j < 4; j++)
            #pragma unroll
            for (int q = 0; q < 4; q++) c[i][j][q] = 0.f;

    {   // prologue chunk 0
        wcopy_async(0, sb, tid);
        CPCOMMIT();
        char* sh = smb + SOFF;
        char* sl = smb + SOFF + SMATB;
        Slot2 s;
        #pragma unroll
        for (int j = 0; j < 2; j++) {
            gather_slot(s, 0, wpx + j * 4, xtb, chl, sct);
            combine_slot(s, sh, sl, wpx + j * 4, chl);
        }
        CPWAIT0();
        __syncthreads();
    }

    for (int t = 0; t < NCHUNK; t++) {
        const int s = t & 1;
        const int ns = s ^ 1;
        const uint32_t stg = sb + (uint32_t)(s * STAGEB);
        char* nsh = smb + ns * STAGEB + SOFF;
        char* nsl = smb + ns * STAGEB + SOFF + SMATB;

        Slot2 s0, s1;
        const int u = t + 1;
        const int tap = u >> 1;
        const float* __restrict__ xq = xtb + ((u & 1) << 5);

        if (t < NCHUNK - 1) {
            wcopy_async(u, sb + (uint32_t)(ns * STAGEB), tid);
            CPCOMMIT();
            gather_slot(s0, tap, wpx + 0, xq, chl, sct);
            gather_slot(s1, tap, wpx + 4, xq, chl, sct);
        }

        do_kstep(stg, 0, warp_m, warp_n, aoffl, boffl, c);

        if (t < NCHUNK - 1) {
            combine_slot(s0, nsh, nsl, wpx + 0, chl);
            combine_slot(s1, nsh, nsl, wpx + 4, chl);
        }

        do_kstep(stg, 1, warp_m, warp_n, aoffl, boffl, c);

        CPWAIT0();
        __syncthreads();
    }

    // Epilogue: fragments -> global
    const int mrow = lid >> 2;
    const int ncol = (lid & 3) * 2;
    #pragma unroll
    for (int i = 0; i < 2; i++) {
        #pragma unroll
        for (int j = 0; j < 4; j++) {
            int m0 = warp_m * 32 + i * 16 + mrow;
            int n  = px0 + warp_n * 32 + j * 8 + ncol;
            float* p0 = out + ((size_t)(b * COUT + m0)) * HWSZ + y * WW + n;
            *(float2*)p0 = make_float2(c[i][j][0], c[i][j][1]);
            *(float2*)(p0 + 8 * HWSZ) = make_float2(c[i][j][2], c[i][j][3]);
        }
    }
}

// ---------------------------------------------------------------------------
extern "C" void kernel_launch(void* const* d_in, const int* in_sizes, int n_in,
                              void* d_out, int out_size)
{
    const float* x     = (const float*)d_in[0];
    const float* w_off = (const float*)d_in[1];
    const float* b_off = (const float*)d_in[2];
    const float* w_mod = (const float*)d_in[3];
    const float* b_mod = (const float*)d_in[4];
    const float* w_reg = (const float*)d_in[5];
    float* out = (float*)d_out;
    (void)in_sizes; (void)n_in; (void)out_size;

    cudaFuncSetAttribute(dcn_kernel, cudaFuncAttributeMaxDynamicSharedMemorySize, SMEMB_TOTAL);

    wprep_kernel<<<(COUT * KTOT + 255) / 256, 256>>>(w_reg);
    wprep_om_kernel<<<(NCHUNK * 32 * 32 + 255) / 256, 256>>>(w_off, w_mod);

    dim3 gT(HWSZ / 64, NB);
    xt_kernel<<<gT, 256>>>(x);

    dim3 gB(2, HH, NB);
    dcn_kernel<<<gB, TBC, SMEMB_TOTAL>>>(b_off, b_mod, out);
}

// round 15
// speedup vs baseline: 3.4252x; 1.3112x over previous
#include <cuda_runtime.h>
#include <cuda_fp16.h>
#include <cstdint>

#define HH 128
#define WW 128
#define HWSZ (HH*WW)
#define CIN 64
#define COUT 128
#define NB 4
#define KTOT 576      // CIN * 9
#define NCHUNK 18     // K chunks of 32

// ---------------- device scratch ----------------
__device__ float g_xt[NB * HWSZ * CIN];         // x transposed: [b][hw][c]
__device__ __half g_wh[NCHUNK * 128 * 32];      // main W (fp16) [chunk][oc][kl]
__device__ __half g_womh[NCHUNK * 32 * 32];     // offset/mod W (fp16)

__device__ __forceinline__ uint32_t smem_u32(const void* p) {
    uint32_t a;
    asm("{ .reg .u64 t; cvta.to.shared.u64 t, %1; cvt.u32.u64 %0, t; }" : "=r"(a) : "l"(p));
    return a;
}
__device__ __forceinline__ void ldm4(uint32_t* r, uint32_t addr) {
    asm volatile("ldmatrix.sync.aligned.m8n8.x4.shared.b16 {%0,%1,%2,%3}, [%4];"
                 : "=r"(r[0]), "=r"(r[1]), "=r"(r[2]), "=r"(r[3]) : "r"(addr));
}
__device__ __forceinline__ void mma_fp16(float* c, const uint32_t* a, const uint32_t* b) {
    asm volatile("mma.sync.aligned.m16n8k16.row.col.f32.f16.f16.f32 "
                 "{%0,%1,%2,%3}, {%4,%5,%6,%7}, {%8,%9}, {%0,%1,%2,%3};"
                 : "+f"(c[0]), "+f"(c[1]), "+f"(c[2]), "+f"(c[3])
                 : "r"(a[0]), "r"(a[1]), "r"(a[2]), "r"(a[3]), "r"(b[0]), "r"(b[1]));
}
__device__ __forceinline__ void cp16(uint32_t dst, const void* src) {
    asm volatile("cp.async.cg.shared.global [%0], [%1], 16;" :: "r"(dst), "l"(src));
}
#define CPCOMMIT() asm volatile("cp.async.commit_group;" ::: "memory")
#define CPWAIT0()  asm volatile("cp.async.wait_group 0;" ::: "memory")

// ---------------- packed f32x2 helpers ----------------
__device__ __forceinline__ uint64_t packw2(float w) {
    uint64_t d; asm("mov.b64 %0, {%1, %1};" : "=l"(d) : "f"(w)); return d;
}
__device__ __forceinline__ uint64_t mul2(uint64_t a, uint64_t b) {
    uint64_t d; asm("mul.rn.f32x2 %0, %1, %2;" : "=l"(d) : "l"(a), "l"(b)); return d;
}
__device__ __forceinline__ uint64_t fma2(uint64_t a, uint64_t b, uint64_t c) {
    uint64_t d; asm("fma.rn.f32x2 %0, %1, %2, %3;" : "=l"(d) : "l"(a), "l"(b), "l"(c)); return d;
}
__device__ __forceinline__ uint32_t cvt_f16x2(uint64_t v) {
    uint32_t r;
    asm("{ .reg .b32 lo, hi; mov.b64 {lo, hi}, %1; cvt.rn.f16x2.f32 %0, hi, lo; }"
        : "=r"(r) : "l"(v));
    return r;
}
__device__ __forceinline__ uint64_t h16x2_to_f32x2(uint32_t h) {
    uint64_t d;
    asm("{ .reg .b16 a, b; .reg .b32 f0, f1; mov.b32 {a, b}, %1; "
        "cvt.f32.f16 f0, a; cvt.f32.f16 f1, b; mov.b64 %0, {f0, f1}; }"
        : "=l"(d) : "r"(h));
    return d;
}
#define NEG1X2 0xBF800000BF800000ULL

// ---------------------------------------------------------------------------
// x transpose: [b][c][hw] -> [b][hw][c]
// ---------------------------------------------------------------------------
__global__ void xt_kernel(const float* __restrict__ x) {
    __shared__ float sm[64][65];
    const int tid = threadIdx.x;
    const int b   = blockIdx.y;
    const int hw0 = blockIdx.x * 64;
    const float* xb = x + (size_t)b * CIN * HWSZ;
    #pragma unroll
    for (int it = 0; it < 16; it++) {
        int c   = (tid >> 6) + it * 4;
        int hwl = tid & 63;
        sm[hwl][c] = xb[c * HWSZ + hw0 + hwl];
    }
    __syncthreads();
    float* xtb = g_xt + ((size_t)b * HWSZ + hw0) * CIN;
    #pragma unroll
    for (int it = 0; it < 16; it++) {
        int hwl = (tid >> 6) + it * 4;
        int cl  = tid & 63;
        xtb[hwl * CIN + cl] = sm[hwl][cl];
    }
}

// ---------------------------------------------------------------------------
// W prep (main conv): fp16, K reordered as k_new = tap*64 + c
// ---------------------------------------------------------------------------
__global__ void wprep_kernel(const float* __restrict__ w_reg) {
    int i = blockIdx.x * 256 + threadIdx.x;
    if (i >= COUT * KTOT) return;
    int oc = i / KTOT;
    int kn = i - oc * KTOT;
    int tap = kn >> 6;
    int c   = kn & 63;
    float v = w_reg[oc * KTOT + c * 9 + tap];
    int chunk = kn >> 5;
    int kl    = kn & 31;
    g_wh[(chunk * 128 + oc) * 32 + kl] = __float2half_rn(v);
}

// ---------------------------------------------------------------------------
// W prep (offset+modulator conv): rows 0-17 = w_off, 18-26 = w_mod, 27-31 = 0
// ---------------------------------------------------------------------------
__global__ void wprep_om_kernel(const float* __restrict__ w_off,
                                const float* __restrict__ w_mod) {
    int i = blockIdx.x * 256 + threadIdx.x;
    if (i >= NCHUNK * 32 * 32) return;
    int chunk = i >> 10;
    int oc    = (i >> 5) & 31;
    int kl    = i & 31;
    int kn  = chunk * 32 + kl;
    int tap = kn >> 6;
    int c   = kn & 63;
    float v = 0.f;
    if (oc < 18)      v = w_off[(oc * CIN + c) * 9 + tap];
    else if (oc < 27) v = w_mod[((oc - 18) * CIN + c) * 9 + tap];
    g_womh[(chunk * 32 + oc) * 32 + kl] = __float2half_rn(v);
}

// ---------------------------------------------------------------------------
// Fused kernel layout (fp16 2-pass: W hi only, S hi+lo)
// ---------------------------------------------------------------------------
#define TBC 256
#define NPX 64
#define ROWB 80
#define WMATB (128 * ROWB)      // 10240: W (hi only)
#define SMATB (NPX * ROWB)      // 5120
#define STAGEB (WMATB + 2 * SMATB)   // 20480: W | Shi | Slo
#define SOFF   WMATB
#define W1MATB (32 * ROWB)      // 2560
#define S1OFF  W1MATB           // 2560: S1 hi at 2560, S1 lo at 2560+5120
#define CWB (2 * STAGEB)        // 40960: float2 (w, idx-bits) tables, 4 planes
#define NTAB (9 * NPX)          // 576
#define OMB (CWB + 4 * NTAB * 8)           // 59392
#define OMSTRIDE 68
#define SMEMB_TOTAL (OMB + 32 * OMSTRIDE * 4)   // 68096

struct Slot2 {
    ulonglong2 a[4];
    float w[4];
};

__device__ __forceinline__ void gather_slot(Slot2& s, int tap, int px, const float* __restrict__ xq,
                                            int chl, const float2* sct) {
    int idx = tap * NPX + px;
    #pragma unroll
    for (int c = 0; c < 4; c++) {
        float2 t = sct[c * NTAB + idx];
        s.w[c] = t.x;
        int lin = __float_as_int(t.y);
        s.a[c] = *(const ulonglong2*)(xq + (size_t)lin * CIN + chl * 4);
    }
}

__device__ __forceinline__ void split_store2(uint64_t v01, uint64_t v23,
                                             char* sh, char* sl, int px, int chl) {
    uint32_t h01 = cvt_f16x2(v01);
    uint32_t h23 = cvt_f16x2(v23);
    uint64_t l01 = fma2(h16x2_to_f32x2(h01), NEG1X2, v01);
    uint64_t l23 = fma2(h16x2_to_f32x2(h23), NEG1X2, v23);
    *(uint2*)(sh + px * ROWB + chl * 8) = make_uint2(h01, h23);
    *(uint2*)(sl + px * ROWB + chl * 8) = make_uint2(cvt_f16x2(l01), cvt_f16x2(l23));
}

__device__ __forceinline__ void combine_slot(const Slot2& s, char* sh, char* sl, int px, int chl) {
    uint64_t w0 = packw2(s.w[0]);
    uint64_t w1 = packw2(s.w[1]);
    uint64_t w2 = packw2(s.w[2]);
    uint64_t w3 = packw2(s.w[3]);
    uint64_t v01 = mul2(w0, s.a[0].x);
    v01 = fma2(w1, s.a[1].x, v01);
    v01 = fma2(w2, s.a[2].x, v01);
    v01 = fma2(w3, s.a[3].x, v01);
    uint64_t v23 = mul2(w0, s.a[0].y);
    v23 = fma2(w1, s.a[1].y, v23);
    v23 = fma2(w2, s.a[2].y, v23);
    v23 = fma2(w3, s.a[3].y, v23);
    split_store2(v01, v23, sh, sl, px, chl);
}

__device__ __forceinline__ void wcopy_async(int chunk, uint32_t stg, int tid) {
    const char* srcH = (const char*)g_wh + (size_t)chunk * 128 * 64;
    #pragma unroll
    for (int it = 0; it < 2; it++) {
        int i = tid + it * TBC;      // 0..511
        int rr = i >> 2;             // 0..127
        int c4 = i & 3;
        cp16(stg + (uint32_t)(rr * ROWB + c4 * 16), srcH + rr * 64 + c4 * 16);
    }
}

__device__ __forceinline__ void w1copy_async(int chunk, uint32_t stg, int tid) {
    // 32 rows x 4 float4 = 128 cp16
    if (tid < 128) {
        int rr = tid >> 2;
        int c4 = tid & 3;
        const char* src = (const char*)g_womh + (size_t)chunk * 2048 + rr * 64 + c4 * 16;
        cp16(stg + (uint32_t)(rr * ROWB + c4 * 16), src);
    }
}

__device__ __forceinline__ void do_kstep(uint32_t stg, int ks, int warp_m, int warp_n,
                                         uint32_t aoffl, uint32_t boffl, float c[2][4][4]) {
    const uint32_t abase = stg + (uint32_t)(warp_m * 32 * ROWB + ks * 32) + aoffl;
    uint32_t ah[2][4];
    ldm4(ah[0], abase);
    ldm4(ah[1], abase + 16 * ROWB);
    const uint32_t bbase = stg + (uint32_t)(SOFF + warp_n * 32 * ROWB + ks * 32) + boffl;
    uint32_t bh[4][2], bl[4][2];
    #pragma unroll
    for (int jj = 0; jj < 2; jj++) {
        uint32_t tmp[4];
        ldm4(tmp, bbase + (uint32_t)(jj * 16 * ROWB));
        bh[2*jj][0] = tmp[0]; bh[2*jj][1] = tmp[1];
        bh[2*jj+1][0] = tmp[2]; bh[2*jj+1][1] = tmp[3];
        ldm4(tmp, bbase + (uint32_t)(SMATB + jj * 16 * ROWB));
        bl[2*jj][0] = tmp[0]; bl[2*jj][1] = tmp[1];
        bl[2*jj+1][0] = tmp[2]; bl[2*jj+1][1] = tmp[3];
    }
    #pragma unroll
    for (int i = 0; i < 2; i++) {
        #pragma unroll
        for (int j = 0; j < 4; j++) {
            mma_fp16(c[i][j], ah[i], bh[j]);
            mma_fp16(c[i][j], ah[i], bl[j]);
        }
    }
}

__device__ __forceinline__ void do_kstep1(uint32_t stg, int ks, uint32_t aoffl,
                                          const uint32_t bh4[4], const uint32_t bl4[4],
                                          float c1[2][4]) {
    const uint32_t abase = stg + (uint32_t)(ks * 32) + aoffl;
    uint32_t ah[2][4];
    ldm4(ah[0], abase);
    ldm4(ah[1], abase + 16 * ROWB);
    uint32_t bh[2] = { bh4[2*ks], bh4[2*ks+1] };
    uint32_t bl[2] = { bl4[2*ks], bl4[2*ks+1] };
    #pragma unroll
    for (int i = 0; i < 2; i++) {
        mma_fp16(c1[i], ah[i], bh);
        mma_fp16(c1[i], ah[i], bl);
    }
}

__global__ void __launch_bounds__(TBC, 2) dcn_kernel(const float* __restrict__ b_off,
                                                     const float* __restrict__ b_mod,
                                                     float* __restrict__ out)
{
    extern __shared__ char smb[];
    const uint32_t sb = smem_u32(smb);
    float2* sct = (float2*)(smb + CWB);
    float*  som = (float*)(smb + OMB);

    const int tid  = threadIdx.x;
    const int wid  = tid >> 5;
    const int lid  = tid & 31;
    const int half = blockIdx.x;
    const int y    = blockIdx.y;
    const int b    = blockIdx.z;
    const int px0  = half * NPX;
    const float* __restrict__ xtb = g_xt + (size_t)b * HWSZ * CIN;

    // Lane maps (shared by both loops)
    const int warp_m = wid & 3;
    const int warp_n = wid >> 2;
    const uint32_t aoffl = (uint32_t)((lid & 15) * ROWB + (lid >> 4) * 16);
    const uint32_t boffl = (uint32_t)(((lid & 7) + ((lid >> 4) ? 8 : 0)) * ROWB + ((lid >> 3) & 1) * 16);
    const int chl = lid & 7;
    const int wpx = wid * 8 + (lid >> 3);
    const uint32_t b1offl = (uint32_t)((wid * 8 + (lid & 7)) * ROWB + (lid >> 3) * 16);

    // plain (non-deformed) im2col load for loop1
    auto plain_load = [&](int px_l, int tap, int cg) -> ulonglong2 {
        int gy = y + tap / 3 - 1;
        int gx = px0 + px_l + tap % 3 - 1;
        if (gy >= 0 && gy < HH && gx >= 0 && gx < WW)
            return *(const ulonglong2*)(xtb + (size_t)(gy * WW + gx) * CIN + cg * 32 + chl * 4);
        ulonglong2 z; z.x = 0ULL; z.y = 0ULL;
        return z;
    };

    // ---------------- Loop 1: offset/modulator GEMM (M=32, N=64, K=576) ----
    float c1[2][4];
    #pragma unroll
    for (int i = 0; i < 2; i++)
        #pragma unroll
        for (int q = 0; q < 4; q++) c1[i][q] = 0.f;

    {   // prologue chunk 0
        w1copy_async(0, sb, tid);
        CPCOMMIT();
        char* sh = smb + S1OFF;
        char* sl = smb + S1OFF + SMATB;
        #pragma unroll
        for (int j = 0; j < 2; j++) {
            ulonglong2 v = plain_load(wpx + j * 4, 0, 0);
            split_store2(v.x, v.y, sh, sl, wpx + j * 4, chl);
        }
        CPWAIT0();
        __syncthreads();
    }

    for (int t = 0; t < NCHUNK; t++) {
        const int s = t & 1;
        const int ns = s ^ 1;
        const uint32_t stg = sb + (uint32_t)(s * STAGEB);
        char* nsh = smb + ns * STAGEB + S1OFF;
        char* nsl = smb + ns * STAGEB + S1OFF + SMATB;

        ulonglong2 v0, v1;
        if (t < NCHUNK - 1) {
            const int u = t + 1;
            w1copy_async(u, sb + (uint32_t)(ns * STAGEB), tid);
            CPCOMMIT();
            v0 = plain_load(wpx + 0, u >> 1, u & 1);
            v1 = plain_load(wpx + 4, u >> 1, u & 1);
        }

        uint32_t bh4[4], bl4[4];
        ldm4(bh4, stg + (uint32_t)S1OFF + b1offl);
        ldm4(bl4, stg + (uint32_t)(S1OFF + SMATB) + b1offl);

        do_kstep1(stg, 0, aoffl, bh4, bl4, c1);

        if (t < NCHUNK - 1) {
            split_store2(v0.x, v0.y, nsh, nsl, wpx + 0, chl);
            split_store2(v1.x, v1.y, nsh, nsl, wpx + 4, chl);
        }

        do_kstep1(stg, 1, aoffl, bh4, bl4, c1);

        CPWAIT0();
        __syncthreads();
    }

    // write om fragments -> smem with bias + sigmoid
    {
        const int r0 = (lid >> 2);
        const int c0 = wid * 8 + (lid & 3) * 2;
        #pragma unroll
        for (int i = 0; i < 2; i++) {
            #pragma unroll
            for (int h2 = 0; h2 < 2; h2++) {
                int row = i * 16 + h2 * 8 + r0;
                float va = c1[i][h2 * 2 + 0];
                float vb = c1[i][h2 * 2 + 1];
                float bias = (row < 18) ? b_off[row] : (row < 27 ? b_mod[row - 18] : 0.f);
                va += bias; vb += bias;
                if (row >= 18 && row < 27) {
                    va = 2.f / (1.f + __expf(-va));
                    vb = 2.f / (1.f + __expf(-vb));
                }
                som[row * OMSTRIDE + c0]     = va;
                som[row * OMSTRIDE + c0 + 1] = vb;
            }
        }
    }
    __syncthreads();

    // ---------------- tables: bilinear coords from smem om ----------------
    for (int i = tid; i < NTAB; i += TBC) {
        int k = i / NPX;
        int p = i - k * NPX;
        int gx = px0 + p;
        float dy = som[(2*k)   * OMSTRIDE + p];
        float dx = som[(2*k+1) * OMSTRIDE + p];
        float m  = som[(18+k)  * OMSTRIDE + p];
        float pyf = (float)(y  + k / 3 - 1) + dy;
        float pxf = (float)(gx + k % 3 - 1) + dx;
        float fy = floorf(pyf);
        float fx = floorf(pxf);
        float ty = pyf - fy;
        float tx = pxf - fx;
        int iy0 = (int)fy, ix0 = (int)fx;
        int iy1 = iy0 + 1, ix1 = ix0 + 1;
        float vy0 = (iy0 >= 0 && iy0 <= HH-1) ? 1.f : 0.f;
        float vy1 = (iy1 >= 0 && iy1 <= HH-1) ? 1.f : 0.f;
        float vx0 = (ix0 >= 0 && ix0 <= WW-1) ? 1.f : 0.f;
        float vx1 = (ix1 >= 0 && ix1 <= WW-1) ? 1.f : 0.f;
        int cy0 = min(max(iy0, 0), HH-1);
        int cy1 = min(max(iy1, 0), HH-1);
        int cx0 = min(max(ix0, 0), WW-1);
        int cx1 = min(max(ix1, 0), WW-1);
        sct[i         ] = make_float2((1.f - ty) * (1.f - tx) * m * vy0 * vx0, __int_as_float(cy0 * WW + cx0));
        sct[NTAB   + i] = make_float2((1.f - ty) * tx         * m * vy0 * vx1, __int_as_float(cy0 * WW + cx1));
        sct[2*NTAB + i] = make_float2(ty * (1.f - tx)         * m * vy1 * vx0, __int_as_float(cy1 * WW + cx0));
        sct[3*NTAB + i] = make_float2(ty * tx                 * m * vy1 * vx1, __int_as_float(cy1 * WW + cx1));
    }
    __syncthreads();

    // ---------------- Loop 2: main deformable GEMM (M=128, N=64, K=576) ----
    float c[2][4][4];
    #pragma unroll
    for (int i = 0; i < 2; i++)
        #pragma unroll
        for (int j = 0; j < 4; j++)
            #pragma unroll
            for (int q = 0; q < 4; q++) c[i][j][q] = 0.f;

    {   // prologue chunk 0
        wcopy_async(0, sb, tid);
        CPCOMMIT();
        char* sh = smb + SOFF;
        char* sl = smb + SOFF + SMATB;
        Slot2 s;
        #pragma unroll
        for (int j = 0; j < 2; j++) {
            gather_slot(s, 0, wpx + j * 4, xtb, chl, sct);
            combine_slot(s, sh, sl, wpx + j * 4, chl);
        }
        CPWAIT0();
        __syncthreads();
    }

    for (int t = 0; t < NCHUNK; t++) {
        const int s = t & 1;
        const int ns = s ^ 1;
        const uint32_t stg = sb + (uint32_t)(s * STAGEB);
        char* nsh = smb + ns * STAGEB + SOFF;
        char* nsl = smb + ns * STAGEB + SOFF + SMATB;

        Slot2 s0, s1;
        const int u = t + 1;
        const int tap = u >> 1;
        const float* __restrict__ xq = xtb + ((u & 1) << 5);

        if (t < NCHUNK - 1) {
            wcopy_async(u, sb + (uint32_t)(ns * STAGEB), tid);
            CPCOMMIT();
            gather_slot(s0, tap, wpx + 0, xq, chl, sct);
            gather_slot(s1, tap, wpx + 4, xq, chl, sct);
        }

        do_kstep(stg, 0, warp_m, warp_n, aoffl, boffl, c);

        if (t < NCHUNK - 1) {
            combine_slot(s0, nsh, nsl, wpx + 0, chl);
            combine_slot(s1, nsh, nsl, wpx + 4, chl);
        }

        do_kstep(stg, 1, warp_m, warp_n, aoffl, boffl, c);

        CPWAIT0();
        __syncthreads();
    }

    // Epilogue: fragments -> global
    const int mrow = lid >> 2;
    const int ncol = (lid & 3) * 2;
    #pragma unroll
    for (int i = 0; i < 2; i++) {
        #pragma unroll
        for (int j = 0; j < 4; j++) {
            int m0 = warp_m * 32 + i * 16 + mrow;
            int n  = px0 + warp_n * 32 + j * 8 + ncol;
            float* p0 = out + ((size_t)(b * COUT + m0)) * HWSZ + y * WW + n;
            *(float2*)p0 = make_float2(c[i][j][0], c[i][j][1]);
            *(float2*)(p0 + 8 * HWSZ) = make_float2(c[i][j][2], c[i][j][3]);
        }
    }
}

// ---------------------------------------------------------------------------
extern "C" void kernel_launch(void* const* d_in, const int* in_sizes, int n_in,
                              void* d_out, int out_size)
{
    const float* x     = (const float*)d_in[0];
    const float* w_off = (const float*)d_in[1];
    const float* b_off = (const float*)d_in[2];
    const float* w_mod = (const float*)d_in[3];
    const float* b_mod = (const float*)d_in[4];
    const float* w_reg = (const float*)d_in[5];
    float* out = (float*)d_out;
    (void)in_sizes; (void)n_in; (void)out_size;

    cudaFuncSetAttribute(dcn_kernel, cudaFuncAttributeMaxDynamicSharedMemorySize, SMEMB_TOTAL);

    wprep_kernel<<<(COUT * KTOT + 255) / 256, 256>>>(w_reg);
    wprep_om_kernel<<<(NCHUNK * 32 * 32 + 255) / 256, 256>>>(w_off, w_mod);

    dim3 gT(HWSZ / 64, NB);
    xt_kernel<<<gT, 256>>>(x);

    dim3 gB(2, HH, NB);
    dcn_kernel<<<gB, TBC, SMEMB_TOTAL>>>(b_off, b_mod, out);
}

// round 16
// speedup vs baseline: 4.3710x; 1.2761x over previous
#include <cuda_runtime.h>
#include <cuda_fp16.h>
#include <cstdint>

#define HH 128
#define WW 128
#define HWSZ (HH*WW)
#define CIN 64
#define COUT 128
#define NB 4
#define KTOT 576      // CIN * 9
#define NCHUNK 18     // K chunks of 32

// ---------------- device scratch ----------------
__device__ float g_xt[NB * HWSZ * CIN];         // x transposed: [b][hw][c]
__device__ __half g_wh[NCHUNK * 128 * 32];      // main W (fp16) [chunk][oc][kl]
__device__ __half g_womh[NCHUNK * 32 * 32];     // offset/mod W (fp16)

__device__ __forceinline__ uint32_t smem_u32(const void* p) {
    uint32_t a;
    asm("{ .reg .u64 t; cvta.to.shared.u64 t, %1; cvt.u32.u64 %0, t; }" : "=r"(a) : "l"(p));
    return a;
}
__device__ __forceinline__ void ldm4(uint32_t* r, uint32_t addr) {
    asm volatile("ldmatrix.sync.aligned.m8n8.x4.shared.b16 {%0,%1,%2,%3}, [%4];"
                 : "=r"(r[0]), "=r"(r[1]), "=r"(r[2]), "=r"(r[3]) : "r"(addr));
}
__device__ __forceinline__ void mma_fp16(float* c, const uint32_t* a, const uint32_t* b) {
    asm volatile("mma.sync.aligned.m16n8k16.row.col.f32.f16.f16.f32 "
                 "{%0,%1,%2,%3}, {%4,%5,%6,%7}, {%8,%9}, {%0,%1,%2,%3};"
                 : "+f"(c[0]), "+f"(c[1]), "+f"(c[2]), "+f"(c[3])
                 : "r"(a[0]), "r"(a[1]), "r"(a[2]), "r"(a[3]), "r"(b[0]), "r"(b[1]));
}
__device__ __forceinline__ void cp16(uint32_t dst, const void* src) {
    asm volatile("cp.async.cg.shared.global [%0], [%1], 16;" :: "r"(dst), "l"(src));
}
#define CPCOMMIT() asm volatile("cp.async.commit_group;" ::: "memory")
#define CPWAIT0()  asm volatile("cp.async.wait_group 0;" ::: "memory")

// ---------------- packed f32x2 helpers ----------------
__device__ __forceinline__ uint64_t packw2(float w) {
    uint64_t d; asm("mov.b64 %0, {%1, %1};" : "=l"(d) : "f"(w)); return d;
}
__device__ __forceinline__ uint64_t mul2(uint64_t a, uint64_t b) {
    uint64_t d; asm("mul.rn.f32x2 %0, %1, %2;" : "=l"(d) : "l"(a), "l"(b)); return d;
}
__device__ __forceinline__ uint64_t fma2(uint64_t a, uint64_t b, uint64_t c) {
    uint64_t d; asm("fma.rn.f32x2 %0, %1, %2, %3;" : "=l"(d) : "l"(a), "l"(b), "l"(c)); return d;
}
__device__ __forceinline__ uint32_t cvt_f16x2(uint64_t v) {
    uint32_t r;
    asm("{ .reg .b32 lo, hi; mov.b64 {lo, hi}, %1; cvt.rn.f16x2.f32 %0, hi, lo; }"
        : "=r"(r) : "l"(v));
    return r;
}

// ---------------------------------------------------------------------------
// x transpose: [b][c][hw] -> [b][hw][c]
// ---------------------------------------------------------------------------
__global__ void xt_kernel(const float* __restrict__ x) {
    __shared__ float sm[64][65];
    const int tid = threadIdx.x;
    const int b   = blockIdx.y;
    const int hw0 = blockIdx.x * 64;
    const float* xb = x + (size_t)b * CIN * HWSZ;
    #pragma unroll
    for (int it = 0; it < 16; it++) {
        int c   = (tid >> 6) + it * 4;
        int hwl = tid & 63;
        sm[hwl][c] = xb[c * HWSZ + hw0 + hwl];
    }
    __syncthreads();
    float* xtb = g_xt + ((size_t)b * HWSZ + hw0) * CIN;
    #pragma unroll
    for (int it = 0; it < 16; it++) {
        int hwl = (tid >> 6) + it * 4;
        int cl  = tid & 63;
        xtb[hwl * CIN + cl] = sm[hwl][cl];
    }
}

// ---------------------------------------------------------------------------
// W prep (main conv): fp16, K reordered as k_new = tap*64 + c
// ---------------------------------------------------------------------------
__global__ void wprep_kernel(const float* __restrict__ w_reg) {
    int i = blockIdx.x * 256 + threadIdx.x;
    if (i >= COUT * KTOT) return;
    int oc = i / KTOT;
    int kn = i - oc * KTOT;
    int tap = kn >> 6;
    int c   = kn & 63;
    float v = w_reg[oc * KTOT + c * 9 + tap];
    int chunk = kn >> 5;
    int kl    = kn & 31;
    g_wh[(chunk * 128 + oc) * 32 + kl] = __float2half_rn(v);
}

// ---------------------------------------------------------------------------
// W prep (offset+modulator conv): rows 0-17 = w_off, 18-26 = w_mod, 27-31 = 0
// ---------------------------------------------------------------------------
__global__ void wprep_om_kernel(const float* __restrict__ w_off,
                                const float* __restrict__ w_mod) {
    int i = blockIdx.x * 256 + threadIdx.x;
    if (i >= NCHUNK * 32 * 32) return;
    int chunk = i >> 10;
    int oc    = (i >> 5) & 31;
    int kl    = i & 31;
    int kn  = chunk * 32 + kl;
    int tap = kn >> 6;
    int c   = kn & 63;
    float v = 0.f;
    if (oc < 18)      v = w_off[(oc * CIN + c) * 9 + tap];
    else if (oc < 27) v = w_mod[((oc - 18) * CIN + c) * 9 + tap];
    g_womh[(chunk * 32 + oc) * 32 + kl] = __float2half_rn(v);
}

// ---------------------------------------------------------------------------
// Fused kernel layout (fp16 single-pass: W | S only)
// ---------------------------------------------------------------------------
#define TBC 256
#define NPX 64
#define ROWB 80
#define WMATB (128 * ROWB)      // 10240
#define SMATB (NPX * ROWB)      // 5120
#define STAGEB (WMATB + SMATB)  // 15360: W | S
#define SOFF   WMATB
#define W1MATB (32 * ROWB)      // 2560
#define S1OFF  W1MATB           // S1 at 2560 within stage
#define CWB (2 * STAGEB)        // 30720: float2 (w, idx-bits) tables, 4 planes
#define NTAB (9 * NPX)          // 576
#define OMB (CWB + 4 * NTAB * 8)           // 49152
#define OMSTRIDE 68
#define SMEMB_TOTAL (OMB + 32 * OMSTRIDE * 4)   // 57856

struct Slot2 {
    ulonglong2 a[4];
    float w[4];
};

__device__ __forceinline__ void gather_slot(Slot2& s, int tap, int px, const float* __restrict__ xq,
                                            int chl, const float2* sct) {
    int idx = tap * NPX + px;
    #pragma unroll
    for (int c = 0; c < 4; c++) {
        float2 t = sct[c * NTAB + idx];
        s.w[c] = t.x;
        int lin = __float_as_int(t.y);
        s.a[c] = *(const ulonglong2*)(xq + (size_t)lin * CIN + chl * 4);
    }
}

__device__ __forceinline__ void store_f16(uint64_t v01, uint64_t v23,
                                          char* sh, int px, int chl) {
    *(uint2*)(sh + px * ROWB + chl * 8) = make_uint2(cvt_f16x2(v01), cvt_f16x2(v23));
}

__device__ __forceinline__ void combine_slot(const Slot2& s, char* sh, int px, int chl) {
    uint64_t w0 = packw2(s.w[0]);
    uint64_t w1 = packw2(s.w[1]);
    uint64_t w2 = packw2(s.w[2]);
    uint64_t w3 = packw2(s.w[3]);
    uint64_t v01 = mul2(w0, s.a[0].x);
    v01 = fma2(w1, s.a[1].x, v01);
    v01 = fma2(w2, s.a[2].x, v01);
    v01 = fma2(w3, s.a[3].x, v01);
    uint64_t v23 = mul2(w0, s.a[0].y);
    v23 = fma2(w1, s.a[1].y, v23);
    v23 = fma2(w2, s.a[2].y, v23);
    v23 = fma2(w3, s.a[3].y, v23);
    store_f16(v01, v23, sh, px, chl);
}

__device__ __forceinline__ void wcopy_async(int chunk, uint32_t stg, int tid) {
    const char* srcH = (const char*)g_wh + (size_t)chunk * 128 * 64;
    #pragma unroll
    for (int it = 0; it < 2; it++) {
        int i = tid + it * TBC;      // 0..511
        int rr = i >> 2;             // 0..127
        int c4 = i & 3;
        cp16(stg + (uint32_t)(rr * ROWB + c4 * 16), srcH + rr * 64 + c4 * 16);
    }
}

__device__ __forceinline__ void w1copy_async(int chunk, uint32_t stg, int tid) {
    if (tid < 128) {
        int rr = tid >> 2;
        int c4 = tid & 3;
        const char* src = (const char*)g_womh + (size_t)chunk * 2048 + rr * 64 + c4 * 16;
        cp16(stg + (uint32_t)(rr * ROWB + c4 * 16), src);
    }
}

__device__ __forceinline__ void do_kstep(uint32_t stg, int ks, int warp_m, int warp_n,
                                         uint32_t aoffl, uint32_t boffl, float c[2][4][4]) {
    const uint32_t abase = stg + (uint32_t)(warp_m * 32 * ROWB + ks * 32) + aoffl;
    uint32_t ah[2][4];
    ldm4(ah[0], abase);
    ldm4(ah[1], abase + 16 * ROWB);
    const uint32_t bbase = stg + (uint32_t)(SOFF + warp_n * 32 * ROWB + ks * 32) + boffl;
    uint32_t bh[4][2];
    #pragma unroll
    for (int jj = 0; jj < 2; jj++) {
        uint32_t tmp[4];
        ldm4(tmp, bbase + (uint32_t)(jj * 16 * ROWB));
        bh[2*jj][0] = tmp[0]; bh[2*jj][1] = tmp[1];
        bh[2*jj+1][0] = tmp[2]; bh[2*jj+1][1] = tmp[3];
    }
    #pragma unroll
    for (int i = 0; i < 2; i++) {
        #pragma unroll
        for (int j = 0; j < 4; j++) {
            mma_fp16(c[i][j], ah[i], bh[j]);
        }
    }
}

__device__ __forceinline__ void do_kstep1(uint32_t stg, int ks, uint32_t aoffl,
                                          const uint32_t bh4[4], float c1[2][4]) {
    const uint32_t abase = stg + (uint32_t)(ks * 32) + aoffl;
    uint32_t ah[2][4];
    ldm4(ah[0], abase);
    ldm4(ah[1], abase + 16 * ROWB);
    uint32_t bh[2] = { bh4[2*ks], bh4[2*ks+1] };
    #pragma unroll
    for (int i = 0; i < 2; i++) {
        mma_fp16(c1[i], ah[i], bh);
    }
}

__global__ void __launch_bounds__(TBC, 2) dcn_kernel(const float* __restrict__ b_off,
                                                     const float* __restrict__ b_mod,
                                                     float* __restrict__ out)
{
    extern __shared__ char smb[];
    const uint32_t sb = smem_u32(smb);
    float2* sct = (float2*)(smb + CWB);
    float*  som = (float*)(smb + OMB);

    const int tid  = threadIdx.x;
    const int wid  = tid >> 5;
    const int lid  = tid & 31;
    const int half = blockIdx.x;
    const int y    = blockIdx.y;
    const int b    = blockIdx.z;
    const int px0  = half * NPX;
    const float* __restrict__ xtb = g_xt + (size_t)b * HWSZ * CIN;

    // Lane maps (shared by both loops)
    const int warp_m = wid & 3;
    const int warp_n = wid >> 2;
    const uint32_t aoffl = (uint32_t)((lid & 15) * ROWB + (lid >> 4) * 16);
    const uint32_t boffl = (uint32_t)(((lid & 7) + ((lid >> 4) ? 8 : 0)) * ROWB + ((lid >> 3) & 1) * 16);
    const int chl = lid & 7;
    const int wpx = wid * 8 + (lid >> 3);
    const uint32_t b1offl = (uint32_t)((wid * 8 + (lid & 7)) * ROWB + (lid >> 3) * 16);

    // plain (non-deformed) im2col load for loop1
    auto plain_load = [&](int px_l, int tap, int cg) -> ulonglong2 {
        int gy = y + tap / 3 - 1;
        int gx = px0 + px_l + tap % 3 - 1;
        if (gy >= 0 && gy < HH && gx >= 0 && gx < WW)
            return *(const ulonglong2*)(xtb + (size_t)(gy * WW + gx) * CIN + cg * 32 + chl * 4);
        ulonglong2 z; z.x = 0ULL; z.y = 0ULL;
        return z;
    };

    // ---------------- Loop 1: offset/modulator GEMM (M=32, N=64, K=576) ----
    float c1[2][4];
    #pragma unroll
    for (int i = 0; i < 2; i++)
        #pragma unroll
        for (int q = 0; q < 4; q++) c1[i][q] = 0.f;

    {   // prologue chunk 0
        w1copy_async(0, sb, tid);
        CPCOMMIT();
        char* sh = smb + S1OFF;
        #pragma unroll
        for (int j = 0; j < 2; j++) {
            ulonglong2 v = plain_load(wpx + j * 4, 0, 0);
            store_f16(v.x, v.y, sh, wpx + j * 4, chl);
        }
        CPWAIT0();
        __syncthreads();
    }

    for (int t = 0; t < NCHUNK; t++) {
        const int s = t & 1;
        const int ns = s ^ 1;
        const uint32_t stg = sb + (uint32_t)(s * STAGEB);
        char* nsh = smb + ns * STAGEB + S1OFF;

        ulonglong2 v0, v1;
        if (t < NCHUNK - 1) {
            const int u = t + 1;
            w1copy_async(u, sb + (uint32_t)(ns * STAGEB), tid);
            CPCOMMIT();
            v0 = plain_load(wpx + 0, u >> 1, u & 1);
            v1 = plain_load(wpx + 4, u >> 1, u & 1);
        }

        uint32_t bh4[4];
        ldm4(bh4, stg + (uint32_t)S1OFF + b1offl);

        do_kstep1(stg, 0, aoffl, bh4, c1);

        if (t < NCHUNK - 1) {
            store_f16(v0.x, v0.y, nsh, wpx + 0, chl);
            store_f16(v1.x, v1.y, nsh, wpx + 4, chl);
        }

        do_kstep1(stg, 1, aoffl, bh4, c1);

        CPWAIT0();
        __syncthreads();
    }

    // write om fragments -> smem with bias + sigmoid
    {
        const int r0 = (lid >> 2);
        const int c0 = wid * 8 + (lid & 3) * 2;
        #pragma unroll
        for (int i = 0; i < 2; i++) {
            #pragma unroll
            for (int h2 = 0; h2 < 2; h2++) {
                int row = i * 16 + h2 * 8 + r0;
                float va = c1[i][h2 * 2 + 0];
                float vb = c1[i][h2 * 2 + 1];
                float bias = (row < 18) ? b_off[row] : (row < 27 ? b_mod[row - 18] : 0.f);
                va += bias; vb += bias;
                if (row >= 18 && row < 27) {
                    va = 2.f / (1.f + __expf(-va));
                    vb = 2.f / (1.f + __expf(-vb));
                }
                som[row * OMSTRIDE + c0]     = va;
                som[row * OMSTRIDE + c0 + 1] = vb;
            }
        }
    }
    __syncthreads();

    // ---------------- tables: bilinear coords from smem om ----------------
    for (int i = tid; i < NTAB; i += TBC) {
        int k = i / NPX;
        int p = i - k * NPX;
        int gx = px0 + p;
        float dy = som[(2*k)   * OMSTRIDE + p];
        float dx = som[(2*k+1) * OMSTRIDE + p];
        float m  = som[(18+k)  * OMSTRIDE + p];
        float pyf = (float)(y  + k / 3 - 1) + dy;
        float pxf = (float)(gx + k % 3 - 1) + dx;
        float fy = floorf(pyf);
        float fx = floorf(pxf);
        float ty = pyf - fy;
        float tx = pxf - fx;
        int iy0 = (int)fy, ix0 = (int)fx;
        int iy1 = iy0 + 1, ix1 = ix0 + 1;
        float vy0 = (iy0 >= 0 && iy0 <= HH-1) ? 1.f : 0.f;
        float vy1 = (iy1 >= 0 && iy1 <= HH-1) ? 1.f : 0.f;
        float vx0 = (ix0 >= 0 && ix0 <= WW-1) ? 1.f : 0.f;
        float vx1 = (ix1 >= 0 && ix1 <= WW-1) ? 1.f : 0.f;
        int cy0 = min(max(iy0, 0), HH-1);
        int cy1 = min(max(iy1, 0), HH-1);
        int cx0 = min(max(ix0, 0), WW-1);
        int cx1 = min(max(ix1, 0), WW-1);
        sct[i         ] = make_float2((1.f - ty) * (1.f - tx) * m * vy0 * vx0, __int_as_float(cy0 * WW + cx0));
        sct[NTAB   + i] = make_float2((1.f - ty) * tx         * m * vy0 * vx1, __int_as_float(cy0 * WW + cx1));
        sct[2*NTAB + i] = make_float2(ty * (1.f - tx)         * m * vy1 * vx0, __int_as_float(cy1 * WW + cx0));
        sct[3*NTAB + i] = make_float2(ty * tx                 * m * vy1 * vx1, __int_as_float(cy1 * WW + cx1));
    }
    __syncthreads();

    // ---------------- Loop 2: main deformable GEMM (M=128, N=64, K=576) ----
    float c[2][4][4];
    #pragma unroll
    for (int i = 0; i < 2; i++)
        #pragma unroll
        for (int j = 0; j < 4; j++)
            #pragma unroll
            for (int q = 0; q < 4; q++) c[i][j][q] = 0.f;

    {   // prologue chunk 0
        wcopy_async(0, sb, tid);
        CPCOMMIT();
        char* sh = smb + SOFF;
        Slot2 s;
        #pragma unroll
        for (int j = 0; j < 2; j++) {
            gather_slot(s, 0, wpx + j * 4, xtb, chl, sct);
            combine_slot(s, sh, wpx + j * 4, chl);
        }
        CPWAIT0();
        __syncthreads();
    }

    for (int t = 0; t < NCHUNK; t++) {
        const int s = t & 1;
        const int ns = s ^ 1;
        const uint32_t stg = sb + (uint32_t)(s * STAGEB);
        char* nsh = smb + ns * STAGEB + SOFF;

        Slot2 s0, s1;
        const int u = t + 1;
        const int tap = u >> 1;
        const float* __restrict__ xq = xtb + ((u & 1) << 5);

        if (t < NCHUNK - 1) {
            wcopy_async(u, sb + (uint32_t)(ns * STAGEB), tid);
            CPCOMMIT();
            gather_slot(s0, tap, wpx + 0, xq, chl, sct);
            gather_slot(s1, tap, wpx + 4, xq, chl, sct);
        }

        do_kstep(stg, 0, warp_m, warp_n, aoffl, boffl, c);

        if (t < NCHUNK - 1) {
            combine_slot(s0, nsh, wpx + 0, chl);
            combine_slot(s1, nsh, wpx + 4, chl);
        }

        do_kstep(stg, 1, warp_m, warp_n, aoffl, boffl, c);

        CPWAIT0();
        __syncthreads();
    }

    // Epilogue: fragments -> global
    const int mrow = lid >> 2;
    const int ncol = (lid & 3) * 2;
    #pragma unroll
    for (int i = 0; i < 2; i++) {
        #pragma unroll
        for (int j = 0; j < 4; j++) {
            int m0 = warp_m * 32 + i * 16 + mrow;
            int n  = px0 + warp_n * 32 + j * 8 + ncol;
            float* p0 = out + ((size_t)(b * COUT + m0)) * HWSZ + y * WW + n;
            *(float2*)p0 = make_float2(c[i][j][0], c[i][j][1]);
            *(float2*)(p0 + 8 * HWSZ) = make_float2(c[i][j][2], c[i][j][3]);
        }
    }
}

// ---------------------------------------------------------------------------
extern "C" void kernel_launch(void* const* d_in, const int* in_sizes, int n_in,
                              void* d_out, int out_size)
{
    const float* x     = (const float*)d_in[0];
    const float* w_off = (const float*)d_in[1];
    const float* b_off = (const float*)d_in[2];
    const float* w_mod = (const float*)d_in[3];
    const float* b_mod = (const float*)d_in[4];
    const float* w_reg = (const float*)d_in[5];
    float* out = (float*)d_out;
    (void)in_sizes; (void)n_in; (void)out_size;

    cudaFuncSetAttribute(dcn_kernel, cudaFuncAttributeMaxDynamicSharedMemorySize, SMEMB_TOTAL);

    wprep_kernel<<<(COUT * KTOT + 255) / 256, 256>>>(w_reg);
    wprep_om_kernel<<<(NCHUNK * 32 * 32 + 255) / 256, 256>>>(w_off, w_mod);

    dim3 gT(HWSZ / 64, NB);
    xt_kernel<<<gT, 256>>>(x);

    dim3 gB(2, HH, NB);
    dcn_kernel<<<gB, TBC, SMEMB_TOTAL>>>(b_off, b_mod, out);
}